// round 1
// baseline (speedup 1.0000x reference)
#include <cuda_runtime.h>
#include <math.h>

#define SS 2048
#define BB 8
#define DD 1024
#define SB (SS*BB)

static __device__ float g_q[(size_t)SB*DD];
static __device__ float g_k[(size_t)SB*DD];
static __device__ float g_v[(size_t)SB*DD];
static __device__ float g_x[(size_t)SB*DD];
static __device__ float g_p[(size_t)BB*SS*SS];

#define SCALE 0.03125f  /* 1/sqrt(1024) */

// ---------------------------------------------------------------------------
// NT GEMM: C[m,n] = sum_k A[m*lda+k] * W[n*ldw+k] + bias[n]
// Block tile 128x128, BK=8, 256 threads, 8x8 per-thread microtile.
// All dims assumed multiples of 128 (M) / 128 (N) / 8 (K) — true for this problem.
// ---------------------------------------------------------------------------
__global__ void __launch_bounds__(256) gemm_nt_kernel(
    const float* __restrict__ A, const float* __restrict__ W,
    const float* __restrict__ bias, float* __restrict__ C,
    int K, int lda, int ldw, int ldc)
{
    __shared__ float As[8][128];
    __shared__ float Ws[8][128];

    const int tid  = threadIdx.x;
    const int m0   = blockIdx.y * 128;
    const int n0   = blockIdx.x * 128;
    const int row  = tid >> 1;          // 0..127
    const int quad = (tid & 1) * 4;     // 0 or 4
    const int tr   = (tid >> 4) * 8;    // 0..120 step 8
    const int tc   = (tid & 15) * 8;    // 0..120 step 8

    const float* Aptr = A + (size_t)(m0 + row) * lda + quad;
    const float* Wptr = W + (size_t)(n0 + row) * ldw + quad;

    float acc[8][8];
    #pragma unroll
    for (int i = 0; i < 8; i++)
        #pragma unroll
        for (int j = 0; j < 8; j++) acc[i][j] = 0.0f;

    for (int k0 = 0; k0 < K; k0 += 8) {
        float4 av = *(const float4*)(Aptr + k0);
        float4 wv = *(const float4*)(Wptr + k0);
        As[quad + 0][row] = av.x; As[quad + 1][row] = av.y;
        As[quad + 2][row] = av.z; As[quad + 3][row] = av.w;
        Ws[quad + 0][row] = wv.x; Ws[quad + 1][row] = wv.y;
        Ws[quad + 2][row] = wv.z; Ws[quad + 3][row] = wv.w;
        __syncthreads();
        #pragma unroll
        for (int kk = 0; kk < 8; kk++) {
            float4 a0 = *(const float4*)&As[kk][tr];
            float4 a1 = *(const float4*)&As[kk][tr + 4];
            float4 b0 = *(const float4*)&Ws[kk][tc];
            float4 b1 = *(const float4*)&Ws[kk][tc + 4];
            float a[8] = {a0.x, a0.y, a0.z, a0.w, a1.x, a1.y, a1.z, a1.w};
            float b[8] = {b0.x, b0.y, b0.z, b0.w, b1.x, b1.y, b1.z, b1.w};
            #pragma unroll
            for (int i = 0; i < 8; i++)
                #pragma unroll
                for (int j = 0; j < 8; j++)
                    acc[i][j] = fmaf(a[i], b[j], acc[i][j]);
        }
        __syncthreads();
    }

    #pragma unroll
    for (int i = 0; i < 8; i++) {
        const int m = m0 + tr + i;
        #pragma unroll
        for (int j = 0; j < 8; j++) {
            const int n = n0 + tc + j;
            C[(size_t)m * ldc + n] = acc[i][j] + bias[n];
        }
    }
}

// ---------------------------------------------------------------------------
// Scores: per batch b, S[i,j] = SCALE * dot(Q_b[i], K_b[j]), lower-tri tiles only.
// Q/K rows live at stride BB*DD. Output g_p[b][i][j], ldc = SS.
// ---------------------------------------------------------------------------
__global__ void __launch_bounds__(256) scores_kernel()
{
    const int jt = blockIdx.x, it = blockIdx.y, b = blockIdx.z;
    if (jt > it) return;   // strictly above diagonal: never read downstream

    __shared__ float As[8][128];
    __shared__ float Ws[8][128];

    const int tid  = threadIdx.x;
    const int m0   = it * 128;
    const int n0   = jt * 128;
    const int row  = tid >> 1;
    const int quad = (tid & 1) * 4;
    const int tr   = (tid >> 4) * 8;
    const int tc   = (tid & 15) * 8;
    const int ld   = BB * DD;

    const float* Aptr = g_q + (size_t)b * DD + (size_t)(m0 + row) * ld + quad;
    const float* Wptr = g_k + (size_t)b * DD + (size_t)(n0 + row) * ld + quad;
    float* C = g_p + (size_t)b * SS * SS;

    float acc[8][8];
    #pragma unroll
    for (int i = 0; i < 8; i++)
        #pragma unroll
        for (int j = 0; j < 8; j++) acc[i][j] = 0.0f;

    for (int k0 = 0; k0 < DD; k0 += 8) {
        float4 av = *(const float4*)(Aptr + k0);
        float4 wv = *(const float4*)(Wptr + k0);
        As[quad + 0][row] = av.x; As[quad + 1][row] = av.y;
        As[quad + 2][row] = av.z; As[quad + 3][row] = av.w;
        Ws[quad + 0][row] = wv.x; Ws[quad + 1][row] = wv.y;
        Ws[quad + 2][row] = wv.z; Ws[quad + 3][row] = wv.w;
        __syncthreads();
        #pragma unroll
        for (int kk = 0; kk < 8; kk++) {
            float4 a0 = *(const float4*)&As[kk][tr];
            float4 a1 = *(const float4*)&As[kk][tr + 4];
            float4 b0 = *(const float4*)&Ws[kk][tc];
            float4 b1 = *(const float4*)&Ws[kk][tc + 4];
            float a[8] = {a0.x, a0.y, a0.z, a0.w, a1.x, a1.y, a1.z, a1.w};
            float bb[8] = {b0.x, b0.y, b0.z, b0.w, b1.x, b1.y, b1.z, b1.w};
            #pragma unroll
            for (int i = 0; i < 8; i++)
                #pragma unroll
                for (int j = 0; j < 8; j++)
                    acc[i][j] = fmaf(a[i], bb[j], acc[i][j]);
        }
        __syncthreads();
    }

    #pragma unroll
    for (int i = 0; i < 8; i++) {
        const int m = m0 + tr + i;
        #pragma unroll
        for (int j = 0; j < 8; j++) {
            const int n = n0 + tc + j;
            C[(size_t)m * SS + n] = acc[i][j] * SCALE;
        }
    }
}

// ---------------------------------------------------------------------------
// In-place causal row softmax: row (b, i) of g_p. Valid j in [0, i]; zeros the rest.
// ---------------------------------------------------------------------------
__global__ void __launch_bounds__(256) softmax_kernel()
{
    const int i = blockIdx.x, b = blockIdx.y;
    float* rowp = g_p + ((size_t)b * SS + i) * SS;
    const int len = i + 1;
    const int tid = threadIdx.x;

    __shared__ float red[32];

    // max
    float lmax = -INFINITY;
    for (int j = tid; j < len; j += 256) lmax = fmaxf(lmax, rowp[j]);
    #pragma unroll
    for (int o = 16; o > 0; o >>= 1)
        lmax = fmaxf(lmax, __shfl_xor_sync(0xffffffffu, lmax, o));
    if ((tid & 31) == 0) red[tid >> 5] = lmax;
    __syncthreads();
    if (tid < 32) {
        float v = (tid < 8) ? red[tid] : -INFINITY;
        #pragma unroll
        for (int o = 4; o > 0; o >>= 1)
            v = fmaxf(v, __shfl_xor_sync(0xffffffffu, v, o));
        if (tid == 0) red[0] = v;
    }
    __syncthreads();
    const float gmax = red[0];
    __syncthreads();

    // exp + sum
    float lsum = 0.0f;
    for (int j = tid; j < len; j += 256) {
        float e = expf(rowp[j] - gmax);
        rowp[j] = e;
        lsum += e;
    }
    #pragma unroll
    for (int o = 16; o > 0; o >>= 1)
        lsum += __shfl_xor_sync(0xffffffffu, lsum, o);
    if ((tid & 31) == 0) red[tid >> 5] = lsum;
    __syncthreads();
    if (tid < 32) {
        float v = (tid < 8) ? red[tid] : 0.0f;
        #pragma unroll
        for (int o = 4; o > 0; o >>= 1)
            v += __shfl_xor_sync(0xffffffffu, v, o);
        if (tid == 0) red[0] = v;
    }
    __syncthreads();
    const float inv = 1.0f / red[0];

    for (int j = tid; j < len; j += 256) rowp[j] *= inv;
    for (int j = len + tid; j < SS; j += 256) rowp[j] = 0.0f;  // padding for PV GEMM
}

// ---------------------------------------------------------------------------
// PV: per batch, X[i,d] = sum_{j<kmax} P[i,j] * V_b[j,d].  kmax clipped at diagonal.
// P row-major (ldp=SS contiguous), V rows at stride BB*DD. NN GEMM.
// ---------------------------------------------------------------------------
__global__ void __launch_bounds__(256) av_kernel()
{
    const int nt = blockIdx.x, it = blockIdx.y, b = blockIdx.z;

    __shared__ float As[8][128];
    __shared__ float Vs[8][128];

    const int tid  = threadIdx.x;
    const int m0   = it * 128;
    const int n0   = nt * 128;
    const int row  = tid >> 1;
    const int quad = (tid & 1) * 4;
    const int krow = tid >> 5;          // 0..7
    const int kcol = (tid & 31) * 4;    // 0..124 step 4
    const int tr   = (tid >> 4) * 8;
    const int tc   = (tid & 15) * 8;
    const int ldv  = BB * DD;
    const int kmax = m0 + 128;          // rows beyond diag contribute 0 anyway

    const float* P = g_p + (size_t)b * SS * SS;
    const float* V = g_v + (size_t)b * DD;
    float* X = g_x + (size_t)b * DD;

    const float* Aptr = P + (size_t)(m0 + row) * SS + quad;

    float acc[8][8];
    #pragma unroll
    for (int i = 0; i < 8; i++)
        #pragma unroll
        for (int j = 0; j < 8; j++) acc[i][j] = 0.0f;

    for (int k0 = 0; k0 < kmax; k0 += 8) {
        float4 av = *(const float4*)(Aptr + k0);
        float4 vv = *(const float4*)(V + (size_t)(k0 + krow) * ldv + n0 + kcol);
        As[quad + 0][row] = av.x; As[quad + 1][row] = av.y;
        As[quad + 2][row] = av.z; As[quad + 3][row] = av.w;
        *(float4*)&Vs[krow][kcol] = vv;
        __syncthreads();
        #pragma unroll
        for (int kk = 0; kk < 8; kk++) {
            float4 a0 = *(const float4*)&As[kk][tr];
            float4 a1 = *(const float4*)&As[kk][tr + 4];
            float4 b0 = *(const float4*)&Vs[kk][tc];
            float4 b1 = *(const float4*)&Vs[kk][tc + 4];
            float a[8] = {a0.x, a0.y, a0.z, a0.w, a1.x, a1.y, a1.z, a1.w};
            float bb[8] = {b0.x, b0.y, b0.z, b0.w, b1.x, b1.y, b1.z, b1.w};
            #pragma unroll
            for (int i = 0; i < 8; i++)
                #pragma unroll
                for (int j = 0; j < 8; j++)
                    acc[i][j] = fmaf(a[i], bb[j], acc[i][j]);
        }
        __syncthreads();
    }

    #pragma unroll
    for (int i = 0; i < 8; i++) {
        const int m = m0 + tr + i;
        #pragma unroll
        for (int j = 0; j < 8; j++) {
            const int n = n0 + tc + j;
            X[(size_t)m * ldv + n] = acc[i][j];
        }
    }
}

// ---------------------------------------------------------------------------
extern "C" void kernel_launch(void* const* d_in, const int* in_sizes, int n_in,
                              void* d_out, int out_size)
{
    const float* query = (const float*)d_in[0];
    const float* key   = (const float*)d_in[1];
    const float* value = (const float*)d_in[2];
    // d_in[3] = mask (int32, causal) — structure is known, not read
    const float* Wq = (const float*)d_in[4];
    const float* bq = (const float*)d_in[5];
    const float* Wk = (const float*)d_in[6];
    const float* bk = (const float*)d_in[7];
    const float* Wv = (const float*)d_in[8];
    const float* bv = (const float*)d_in[9];
    const float* Wo = (const float*)d_in[10];
    const float* bo = (const float*)d_in[11];
    float* out = (float*)d_out;

    float *qb, *kb, *vb, *xb;
    cudaGetSymbolAddress((void**)&qb, g_q);
    cudaGetSymbolAddress((void**)&kb, g_k);
    cudaGetSymbolAddress((void**)&vb, g_v);
    cudaGetSymbolAddress((void**)&xb, g_x);

    // Projections: [SB, DD] x [DD, DD]^T
    dim3 gproj(DD / 128, SB / 128);
    gemm_nt_kernel<<<gproj, 256>>>(query, Wq, bq, qb, DD, DD, DD, DD);
    gemm_nt_kernel<<<gproj, 256>>>(key,   Wk, bk, kb, DD, DD, DD, DD);
    gemm_nt_kernel<<<gproj, 256>>>(value, Wv, bv, vb, DD, DD, DD, DD);

    // Causal scores
    dim3 gsc(SS / 128, SS / 128, BB);
    scores_kernel<<<gsc, 256>>>();

    // Softmax
    dim3 gsm(SS, BB);
    softmax_kernel<<<gsm, 256>>>();

    // P @ V
    dim3 gav(DD / 128, SS / 128, BB);
    av_kernel<<<gav, 256>>>();

    // Output projection -> d_out
    gemm_nt_kernel<<<gproj, 256>>>(xb, Wo, bo, out, DD, DD, DD, DD);
}

// round 2
// speedup vs baseline: 2.4042x; 2.4042x over previous
#include <cuda_runtime.h>
#include <math.h>
#include <stdint.h>

#define SS 2048
#define BB 8
#define DD 1024
#define SB (SS*BB)
#define SCALE 0.03125f  /* 1/sqrt(1024) */
#define LST 20          /* smem row stride in words (16 + 4 pad, keeps 16B alignment) */

static __device__ float g_q[(size_t)SB*DD];
static __device__ float g_k[(size_t)SB*DD];
static __device__ float g_v[(size_t)SB*DD];
static __device__ float g_x[(size_t)SB*DD];
static __device__ float g_p[(size_t)BB*SS*SS];

__device__ __forceinline__ uint32_t f2tf(float f) {
    uint32_t u;
    asm("cvt.rna.tf32.f32 %0, %1;" : "=r"(u) : "f"(f));
    return u;
}

__device__ __forceinline__ void mma8(float* c, const uint32_t* a, const uint32_t* b) {
    asm volatile(
        "mma.sync.aligned.m16n8k8.row.col.f32.tf32.tf32.f32 "
        "{%0,%1,%2,%3}, {%4,%5,%6,%7}, {%8,%9}, {%0,%1,%2,%3};"
        : "+f"(c[0]), "+f"(c[1]), "+f"(c[2]), "+f"(c[3])
        : "r"(a[0]), "r"(a[1]), "r"(a[2]), "r"(a[3]), "r"(b[0]), "r"(b[1]));
}

// ---------------------------------------------------------------------------
// Templated tensor-core GEMM, 128x128 CTA tile, BK=16, 256 threads (8 warps 2x4).
// MODE 0: C = A @ W^T + bias      (projections; A [M,DD], W [DD,DD], row-major)
// MODE 1: scores = SCALE * Qb @ Kb^T, causal tile skip  (strided rows, C=g_p)
// MODE 2: X = P @ Vb (NN, V transposed at STS), K clipped at diagonal
// ---------------------------------------------------------------------------
template<int MODE>
__global__ void __launch_bounds__(256, 2) tc_gemm(
    const float* __restrict__ Ag, const float* __restrict__ Bg,
    const float* __restrict__ bias, float* __restrict__ Cg)
{
    const int bx = blockIdx.x, by = blockIdx.y, bz = blockIdx.z;
    if (MODE == 1 && bx > by) return;   // strictly-upper tiles never read downstream

    const int m0 = by * 128, n0 = bx * 128;

    const float* A; const float* Bp; float* C;
    int lda, ldb, ldc, K;
    if (MODE == 0) {
        A = Ag + (size_t)m0 * DD;          lda = DD;
        Bp = Bg + (size_t)n0 * DD;         ldb = DD;
        C = Cg;                            ldc = DD;
        K = DD;
    } else if (MODE == 1) {
        A = g_q + (size_t)bz * DD + (size_t)m0 * (BB*DD);  lda = BB*DD;
        Bp = g_k + (size_t)bz * DD + (size_t)n0 * (BB*DD); ldb = BB*DD;
        C = g_p + (size_t)bz * SS * SS;    ldc = SS;
        K = DD;
    } else {
        A = g_p + (size_t)bz * SS * SS + (size_t)m0 * SS;  lda = SS;
        Bp = g_v + (size_t)bz * DD + n0;   ldb = BB*DD;    // NN: rows along k
        C = g_x + (size_t)bz * DD;         ldc = BB*DD;
        K = m0 + 128;                       // rows past diagonal contribute 0
    }

    const int tid   = threadIdx.x;
    const int warp  = tid >> 5, lane = tid & 31;
    const int group = lane >> 2, quad = lane & 3;
    const int warp_m = (warp >> 2) * 64;   // 0 or 64
    const int warp_n = (warp & 3) * 32;    // 0..96

    __shared__ uint32_t smA[2][128 * LST];
    __shared__ uint32_t smB[2][128 * LST];

    float4 pa[2], pb[2];

    auto ldgA = [&](int k0) {
        #pragma unroll
        for (int j = 0; j < 2; j++) {
            int idx = tid * 2 + j;
            int row = idx >> 2, c4 = idx & 3;
            pa[j] = *(const float4*)(A + (size_t)row * lda + k0 + c4 * 4);
        }
    };
    auto ldgB = [&](int k0) {
        #pragma unroll
        for (int j = 0; j < 2; j++) {
            int idx = tid * 2 + j;
            if (MODE != 2) {
                int row = idx >> 2, c4 = idx & 3;
                pb[j] = *(const float4*)(Bp + (size_t)row * ldb + k0 + c4 * 4);
            } else {
                int krow = idx >> 5, nf4 = idx & 31;
                pb[j] = *(const float4*)(Bp + (size_t)(k0 + krow) * ldb + nf4 * 4);
            }
        }
    };
    auto stsAB = [&](int buf) {
        #pragma unroll
        for (int j = 0; j < 2; j++) {
            int idx = tid * 2 + j;
            int row = idx >> 2, c4 = idx & 3;
            uint4 ua = make_uint4(f2tf(pa[j].x), f2tf(pa[j].y), f2tf(pa[j].z), f2tf(pa[j].w));
            *(uint4*)&smA[buf][row * LST + c4 * 4] = ua;
            if (MODE != 2) {
                uint4 ub = make_uint4(f2tf(pb[j].x), f2tf(pb[j].y), f2tf(pb[j].z), f2tf(pb[j].w));
                *(uint4*)&smB[buf][row * LST + c4 * 4] = ub;
            } else {
                int krow = idx >> 5, nf4 = idx & 31;
                smB[buf][(nf4 * 4 + 0) * LST + krow] = f2tf(pb[j].x);
                smB[buf][(nf4 * 4 + 1) * LST + krow] = f2tf(pb[j].y);
                smB[buf][(nf4 * 4 + 2) * LST + krow] = f2tf(pb[j].z);
                smB[buf][(nf4 * 4 + 3) * LST + krow] = f2tf(pb[j].w);
            }
        }
    };

    float acc[4][4][4];
    #pragma unroll
    for (int mi = 0; mi < 4; mi++)
        #pragma unroll
        for (int ni = 0; ni < 4; ni++)
            #pragma unroll
            for (int r = 0; r < 4; r++) acc[mi][ni][r] = 0.0f;

    auto compute = [&](int buf) {
        #pragma unroll
        for (int ks = 0; ks < 2; ks++) {
            const int kb = ks * 8;
            uint32_t af[4][4], bf[4][2];
            #pragma unroll
            for (int mi = 0; mi < 4; mi++) {
                int mb = (warp_m + mi * 16 + group) * LST + kb + quad;
                af[mi][0] = smA[buf][mb];
                af[mi][1] = smA[buf][mb + 8 * LST];
                af[mi][2] = smA[buf][mb + 4];
                af[mi][3] = smA[buf][mb + 8 * LST + 4];
            }
            #pragma unroll
            for (int ni = 0; ni < 4; ni++) {
                int nb = (warp_n + ni * 8 + group) * LST + kb + quad;
                bf[ni][0] = smB[buf][nb];
                bf[ni][1] = smB[buf][nb + 4];
            }
            #pragma unroll
            for (int mi = 0; mi < 4; mi++)
                #pragma unroll
                for (int ni = 0; ni < 4; ni++)
                    mma8(acc[mi][ni], af[mi], bf[ni]);
        }
    };

    // pipeline
    ldgA(0); ldgB(0); stsAB(0);
    __syncthreads();
    int buf = 0;
    for (int k0 = 16; k0 < K; k0 += 16) {
        ldgA(k0); ldgB(k0);
        compute(buf);
        stsAB(buf ^ 1);
        __syncthreads();
        buf ^= 1;
    }
    compute(buf);

    // epilogue
    #pragma unroll
    for (int mi = 0; mi < 4; mi++) {
        const int mrow = m0 + warp_m + mi * 16 + group;
        #pragma unroll
        for (int ni = 0; ni < 4; ni++) {
            const int ncol = n0 + warp_n + ni * 8 + quad * 2;
            const float* c = acc[mi][ni];
            if (MODE == 0) {
                float2 bv = *(const float2*)(bias + ncol);
                *(float2*)(C + (size_t)mrow * ldc + ncol)       = make_float2(c[0] + bv.x, c[1] + bv.y);
                *(float2*)(C + (size_t)(mrow + 8) * ldc + ncol) = make_float2(c[2] + bv.x, c[3] + bv.y);
            } else if (MODE == 1) {
                *(float2*)(C + (size_t)mrow * ldc + ncol)       = make_float2(c[0] * SCALE, c[1] * SCALE);
                *(float2*)(C + (size_t)(mrow + 8) * ldc + ncol) = make_float2(c[2] * SCALE, c[3] * SCALE);
            } else {
                *(float2*)(C + (size_t)mrow * ldc + ncol)       = make_float2(c[0], c[1]);
                *(float2*)(C + (size_t)(mrow + 8) * ldc + ncol) = make_float2(c[2], c[3]);
            }
        }
    }
}

// ---------------------------------------------------------------------------
// In-place causal row softmax over row (b, i) of g_p; zero-fills j in [i+1, SS).
// ---------------------------------------------------------------------------
__global__ void __launch_bounds__(256) softmax_kernel()
{
    const int i = blockIdx.x, b = blockIdx.y;
    float* rowp = g_p + ((size_t)b * SS + i) * SS;
    const int len = i + 1;
    const int tid = threadIdx.x;

    __shared__ float red[32];

    float lmax = -INFINITY;
    for (int j = tid; j < len; j += 256) lmax = fmaxf(lmax, rowp[j]);
    #pragma unroll
    for (int o = 16; o > 0; o >>= 1)
        lmax = fmaxf(lmax, __shfl_xor_sync(0xffffffffu, lmax, o));
    if ((tid & 31) == 0) red[tid >> 5] = lmax;
    __syncthreads();
    if (tid < 32) {
        float v = (tid < 8) ? red[tid] : -INFINITY;
        #pragma unroll
        for (int o = 4; o > 0; o >>= 1)
            v = fmaxf(v, __shfl_xor_sync(0xffffffffu, v, o));
        if (tid == 0) red[0] = v;
    }
    __syncthreads();
    const float gmax = red[0];
    __syncthreads();

    float lsum = 0.0f;
    for (int j = tid; j < len; j += 256) {
        float e = expf(rowp[j] - gmax);
        rowp[j] = e;
        lsum += e;
    }
    #pragma unroll
    for (int o = 16; o > 0; o >>= 1)
        lsum += __shfl_xor_sync(0xffffffffu, lsum, o);
    if ((tid & 31) == 0) red[tid >> 5] = lsum;
    __syncthreads();
    if (tid < 32) {
        float v = (tid < 8) ? red[tid] : 0.0f;
        #pragma unroll
        for (int o = 4; o > 0; o >>= 1)
            v += __shfl_xor_sync(0xffffffffu, v, o);
        if (tid == 0) red[0] = v;
    }
    __syncthreads();
    const float inv = 1.0f / red[0];

    for (int j = tid; j < len; j += 256) rowp[j] *= inv;
    for (int j = len + tid; j < SS; j += 256) rowp[j] = 0.0f;
}

// ---------------------------------------------------------------------------
extern "C" void kernel_launch(void* const* d_in, const int* in_sizes, int n_in,
                              void* d_out, int out_size)
{
    const float* query = (const float*)d_in[0];
    const float* key   = (const float*)d_in[1];
    const float* value = (const float*)d_in[2];
    // d_in[3] = mask (causal; structure known, not read)
    const float* Wq = (const float*)d_in[4];
    const float* bq = (const float*)d_in[5];
    const float* Wk = (const float*)d_in[6];
    const float* bk = (const float*)d_in[7];
    const float* Wv = (const float*)d_in[8];
    const float* bv = (const float*)d_in[9];
    const float* Wo = (const float*)d_in[10];
    const float* bo = (const float*)d_in[11];
    float* out = (float*)d_out;

    float *qb, *kb, *vb, *xb;
    cudaGetSymbolAddress((void**)&qb, g_q);
    cudaGetSymbolAddress((void**)&kb, g_k);
    cudaGetSymbolAddress((void**)&vb, g_v);
    cudaGetSymbolAddress((void**)&xb, g_x);

    dim3 gproj(DD / 128, SB / 128);
    tc_gemm<0><<<gproj, 256>>>(query, Wq, bq, qb);
    tc_gemm<0><<<gproj, 256>>>(key,   Wk, bk, kb);
    tc_gemm<0><<<gproj, 256>>>(value, Wv, bv, vb);

    tc_gemm<1><<<dim3(SS/128, SS/128, BB), 256>>>(nullptr, nullptr, nullptr, nullptr);

    softmax_kernel<<<dim3(SS, BB), 256>>>();

    tc_gemm<2><<<dim3(DD/128, SS/128, BB), 256>>>(nullptr, nullptr, nullptr, nullptr);

    tc_gemm<0><<<gproj, 256>>>(xb, Wo, bo, out);
}

// round 3
// speedup vs baseline: 4.0570x; 1.6874x over previous
#include <cuda_runtime.h>
#include <math.h>
#include <stdint.h>

#define SS 2048
#define BB 8
#define DD 1024
#define SB (SS*BB)
#define SCALE 0.03125f  /* 1/sqrt(1024) */

static __device__ float g_q[(size_t)SB*DD];
static __device__ float g_k[(size_t)SB*DD];
static __device__ float g_v[(size_t)SB*DD];
static __device__ float g_x[(size_t)SB*DD];
static __device__ float g_p[(size_t)BB*SS*SS];
// tf32-rounded copies of raw inputs
static __device__ float g_cq[(size_t)SB*DD];
static __device__ float g_ck[(size_t)SB*DD];
static __device__ float g_cv[(size_t)SB*DD];
static __device__ float g_wq[(size_t)DD*DD];
static __device__ float g_wk[(size_t)DD*DD];
static __device__ float g_wv[(size_t)DD*DD];
static __device__ float g_wo[(size_t)DD*DD];

__device__ __forceinline__ uint32_t f2tf(float f) {
    uint32_t u;
    asm("cvt.rna.tf32.f32 %0, %1;" : "=r"(u) : "f"(f));
    return u;
}
__device__ __forceinline__ float rtf(float f) { return __uint_as_float(f2tf(f)); }

__device__ __forceinline__ void mma8(float* c, const uint32_t* a, const uint32_t* b) {
    asm volatile(
        "mma.sync.aligned.m16n8k8.row.col.f32.tf32.tf32.f32 "
        "{%0,%1,%2,%3}, {%4,%5,%6,%7}, {%8,%9}, {%0,%1,%2,%3};"
        : "+f"(c[0]), "+f"(c[1]), "+f"(c[2]), "+f"(c[3])
        : "r"(a[0]), "r"(a[1]), "r"(a[2]), "r"(a[3]), "r"(b[0]), "r"(b[1]));
}
__device__ __forceinline__ void ldsm4(uint32_t& r0, uint32_t& r1, uint32_t& r2, uint32_t& r3, uint32_t addr) {
    asm volatile("ldmatrix.sync.aligned.m8n8.x4.shared.b16 {%0,%1,%2,%3}, [%4];"
                 : "=r"(r0), "=r"(r1), "=r"(r2), "=r"(r3) : "r"(addr));
}
__device__ __forceinline__ void cpa16(uint32_t s, const void* g) {
    asm volatile("cp.async.cg.shared.global [%0], [%1], 16;" :: "r"(s), "l"(g));
}
#define CP_COMMIT() asm volatile("cp.async.commit_group;")
template<int N> __device__ __forceinline__ void cp_wait() {
    asm volatile("cp.async.wait_group %0;" :: "n"(N));
}

// ---------------------------------------------------------------------------
// Tensor-core GEMM, 128x128 CTA tile, BK=16, 256 threads (8 warps 2x4),
// cp.async multi-stage pipeline + ldmatrix fragment loads.
// All A/B operands are pre-rounded tf32 values stored as fp32 in gmem.
// MODE 0: C = round_tf32(A @ W^T + bias)       (Q/K/V projections)
// MODE 1: scores = SCALE * Qb @ Kb^T  (causal tile skip, fp32 out)
// MODE 2: X = round_tf32(P @ Vb)  (NN; K clipped at diagonal)
// MODE 3: C = A @ W^T + bias  (final projection, fp32 out)
// ---------------------------------------------------------------------------
template<int MODE>
__global__ void __launch_bounds__(256, 2) tc_gemm(
    const float* __restrict__ Ag, const float* __restrict__ Bg,
    const float* __restrict__ bias, float* __restrict__ Cg)
{
    constexpr int ST = (MODE == 2) ? 2 : 3;
    constexpr int AW = 2048;                      // words per A stage (128x16)
    constexpr int BW = (MODE == 2) ? 2176 : 2048; // MODE2: 16 x 136 padded

    const int bx = blockIdx.x, by = blockIdx.y, bz = blockIdx.z;
    if (MODE == 1 && bx > by) return;

    const int m0 = by * 128, n0 = bx * 128;

    const float* A; const float* Bp; float* C;
    int lda, ldb, ldc, K;
    if (MODE == 0 || MODE == 3) {
        A = Ag + (size_t)m0 * DD;          lda = DD;
        Bp = Bg + (size_t)n0 * DD;         ldb = DD;
        C = Cg;                            ldc = DD;
        K = DD;
    } else if (MODE == 1) {
        A = g_q + (size_t)bz * DD + (size_t)m0 * (BB*DD);  lda = BB*DD;
        Bp = g_k + (size_t)bz * DD + (size_t)n0 * (BB*DD); ldb = BB*DD;
        C = g_p + (size_t)bz * SS * SS;    ldc = SS;
        K = DD;
    } else {
        A = g_p + (size_t)bz * SS * SS + (size_t)m0 * SS;  lda = SS;
        Bp = g_v + (size_t)bz * DD + n0;   ldb = BB*DD;
        C = g_x + (size_t)bz * DD;         ldc = BB*DD;
        K = m0 + 128;
    }
    const int KIT = K / 16;

    const int tid   = threadIdx.x;
    const int warp  = tid >> 5, lane = tid & 31;
    const int group = lane >> 2, quad = lane & 3;
    const int warp_m = (warp >> 2) * 64;
    const int warp_n = (warp & 3) * 32;

    __shared__ uint32_t smA[ST * AW];
    __shared__ uint32_t smB[ST * BW];
    const uint32_t smA_u = (uint32_t)__cvta_generic_to_shared(smA);
    const uint32_t smB_u = (uint32_t)__cvta_generic_to_shared(smB);

    // ldmatrix lane address components
    const int sel = lane >> 3, lr = lane & 7;
    const int a_row  = warp_m + (sel & 1) * 8 + lr;   // + mi*16
    const int a_gsel = sel >> 1;
    const int a_sw   = (a_row >> 1) & 3;              // mi*16 doesn't change it
    const int b_nrow = warp_n + (sel >> 1) * 8 + lr;  // + np*16
    const int b_gsel = sel & 1;
    const int b_sw   = (b_nrow >> 1) & 3;

    auto issue = [&](int it) {
        const int k0 = it * 16;
        const int buf = it % ST;
        const uint32_t dA = smA_u + buf * AW * 4;
        const uint32_t dB = smB_u + buf * BW * 4;
        #pragma unroll
        for (int j = 0; j < 2; j++) {
            const int c = tid + 256 * j;
            const int row = c >> 2, g = c & 3;
            const int phys = row * 16 + ((g ^ ((row >> 1) & 3)) << 2);
            cpa16(dA + phys * 4, A + (size_t)row * lda + k0 + g * 4);
            if (MODE != 2) {
                cpa16(dB + phys * 4, Bp + (size_t)row * ldb + k0 + g * 4);
            } else {
                const int krow = c >> 5, ng = c & 31;
                cpa16(dB + (krow * 136 + ng * 4) * 4,
                      Bp + (size_t)(k0 + krow) * ldb + ng * 4);
            }
        }
    };

    float acc[4][4][4];
    #pragma unroll
    for (int mi = 0; mi < 4; mi++)
        #pragma unroll
        for (int ni = 0; ni < 4; ni++)
            #pragma unroll
            for (int r = 0; r < 4; r++) acc[mi][ni][r] = 0.0f;

    auto compute = [&](int buf) {
        const uint32_t bA = smA_u + buf * AW * 4;
        #pragma unroll
        for (int ks = 0; ks < 2; ks++) {
            uint32_t af[4][4];
            #pragma unroll
            for (int mi = 0; mi < 4; mi++) {
                const int row = a_row + mi * 16;
                const uint32_t addr = bA + (row * 16 + (((ks*2 + a_gsel) ^ a_sw) << 2)) * 4;
                ldsm4(af[mi][0], af[mi][1], af[mi][2], af[mi][3], addr);
            }
            uint32_t bf[4][2];
            if (MODE != 2) {
                const uint32_t bB = smB_u + buf * BW * 4;
                #pragma unroll
                for (int np = 0; np < 2; np++) {
                    const int nr = b_nrow + np * 16;
                    const uint32_t addr = bB + (nr * 16 + (((ks*2 + b_gsel) ^ b_sw) << 2)) * 4;
                    ldsm4(bf[np*2][0], bf[np*2][1], bf[np*2+1][0], bf[np*2+1][1], addr);
                }
            } else {
                const uint32_t* sB = smB + buf * BW;
                #pragma unroll
                for (int ni = 0; ni < 4; ni++) {
                    const int n = warp_n + ni * 8 + group;
                    bf[ni][0] = sB[(ks*8 + quad)     * 136 + n];
                    bf[ni][1] = sB[(ks*8 + quad + 4) * 136 + n];
                }
            }
            #pragma unroll
            for (int mi = 0; mi < 4; mi++)
                #pragma unroll
                for (int ni = 0; ni < 4; ni++)
                    mma8(acc[mi][ni], af[mi], bf[ni]);
        }
    };

    // pipeline
    #pragma unroll
    for (int s = 0; s < ST - 1; s++) { issue(s); CP_COMMIT(); }
    for (int it = 0; it < KIT; it++) {
        cp_wait<ST - 2>();
        __syncthreads();
        compute(it % ST);
        if (it + ST - 1 < KIT) issue(it + ST - 1);
        CP_COMMIT();
    }

    // epilogue
    #pragma unroll
    for (int mi = 0; mi < 4; mi++) {
        const int mrow = m0 + warp_m + mi * 16 + group;
        #pragma unroll
        for (int ni = 0; ni < 4; ni++) {
            const int ncol = n0 + warp_n + ni * 8 + quad * 2;
            const float* c = acc[mi][ni];
            float2 o0, o1;
            if (MODE == 0 || MODE == 3) {
                float2 bv = *(const float2*)(bias + ncol);
                if (MODE == 0) {
                    o0 = make_float2(rtf(c[0] + bv.x), rtf(c[1] + bv.y));
                    o1 = make_float2(rtf(c[2] + bv.x), rtf(c[3] + bv.y));
                } else {
                    o0 = make_float2(c[0] + bv.x, c[1] + bv.y);
                    o1 = make_float2(c[2] + bv.x, c[3] + bv.y);
                }
            } else if (MODE == 1) {
                o0 = make_float2(c[0] * SCALE, c[1] * SCALE);
                o1 = make_float2(c[2] * SCALE, c[3] * SCALE);
            } else {
                o0 = make_float2(rtf(c[0]), rtf(c[1]));
                o1 = make_float2(rtf(c[2]), rtf(c[3]));
            }
            *(float2*)(C + (size_t)mrow * ldc + ncol)       = o0;
            *(float2*)(C + (size_t)(mrow + 8) * ldc + ncol) = o1;
        }
    }
}

// ---------------------------------------------------------------------------
// tf32 pre-rounding copy
// ---------------------------------------------------------------------------
__global__ void __launch_bounds__(256) cvt_tf32_kernel(
    const float4* __restrict__ s, float4* __restrict__ d, int n4)
{
    int i = blockIdx.x * 256 + threadIdx.x;
    if (i < n4) {
        float4 v = s[i];
        d[i] = make_float4(rtf(v.x), rtf(v.y), rtf(v.z), rtf(v.w));
    }
}

// ---------------------------------------------------------------------------
// In-place causal row softmax; writes tf32-rounded P, zero-fills j>i.
// ---------------------------------------------------------------------------
__global__ void __launch_bounds__(256) softmax_kernel()
{
    const int i = blockIdx.x, b = blockIdx.y;
    float* rowp = g_p + ((size_t)b * SS + i) * SS;
    const int len = i + 1;
    const int tid = threadIdx.x;

    __shared__ float red[32];

    float lmax = -INFINITY;
    for (int j = tid; j < len; j += 256) lmax = fmaxf(lmax, rowp[j]);
    #pragma unroll
    for (int o = 16; o > 0; o >>= 1)
        lmax = fmaxf(lmax, __shfl_xor_sync(0xffffffffu, lmax, o));
    if ((tid & 31) == 0) red[tid >> 5] = lmax;
    __syncthreads();
    if (tid < 32) {
        float v = (tid < 8) ? red[tid] : -INFINITY;
        #pragma unroll
        for (int o = 4; o > 0; o >>= 1)
            v = fmaxf(v, __shfl_xor_sync(0xffffffffu, v, o));
        if (tid == 0) red[0] = v;
    }
    __syncthreads();
    const float gmax = red[0];
    __syncthreads();

    float lsum = 0.0f;
    for (int j = tid; j < len; j += 256) {
        float e = expf(rowp[j] - gmax);
        rowp[j] = e;
        lsum += e;
    }
    #pragma unroll
    for (int o = 16; o > 0; o >>= 1)
        lsum += __shfl_xor_sync(0xffffffffu, lsum, o);
    if ((tid & 31) == 0) red[tid >> 5] = lsum;
    __syncthreads();
    if (tid < 32) {
        float v = (tid < 8) ? red[tid] : 0.0f;
        #pragma unroll
        for (int o = 4; o > 0; o >>= 1)
            v += __shfl_xor_sync(0xffffffffu, v, o);
        if (tid == 0) red[0] = v;
    }
    __syncthreads();
    const float inv = 1.0f / red[0];

    for (int j = tid; j < len; j += 256) rowp[j] = rtf(rowp[j] * inv);
    for (int j = len + tid; j < SS; j += 256) rowp[j] = 0.0f;
}

// ---------------------------------------------------------------------------
extern "C" void kernel_launch(void* const* d_in, const int* in_sizes, int n_in,
                              void* d_out, int out_size)
{
    const float* query = (const float*)d_in[0];
    const float* key   = (const float*)d_in[1];
    const float* value = (const float*)d_in[2];
    // d_in[3] = causal mask (structure known, not read)
    const float* Wq = (const float*)d_in[4];
    const float* bq = (const float*)d_in[5];
    const float* Wk = (const float*)d_in[6];
    const float* bk = (const float*)d_in[7];
    const float* Wv = (const float*)d_in[8];
    const float* bv = (const float*)d_in[9];
    const float* Wo = (const float*)d_in[10];
    const float* bo = (const float*)d_in[11];
    float* out = (float*)d_out;

    float *qb, *kb, *vb, *xb, *cq, *ck, *cv, *wq, *wk, *wv, *wo;
    cudaGetSymbolAddress((void**)&qb, g_q);
    cudaGetSymbolAddress((void**)&kb, g_k);
    cudaGetSymbolAddress((void**)&vb, g_v);
    cudaGetSymbolAddress((void**)&xb, g_x);
    cudaGetSymbolAddress((void**)&cq, g_cq);
    cudaGetSymbolAddress((void**)&ck, g_ck);
    cudaGetSymbolAddress((void**)&cv, g_cv);
    cudaGetSymbolAddress((void**)&wq, g_wq);
    cudaGetSymbolAddress((void**)&wk, g_wk);
    cudaGetSymbolAddress((void**)&wv, g_wv);
    cudaGetSymbolAddress((void**)&wo, g_wo);

    const int nbig4 = SB * DD / 4, nw4 = DD * DD / 4;
    cvt_tf32_kernel<<<nbig4/256, 256>>>((const float4*)query, (float4*)cq, nbig4);
    cvt_tf32_kernel<<<nbig4/256, 256>>>((const float4*)key,   (float4*)ck, nbig4);
    cvt_tf32_kernel<<<nbig4/256, 256>>>((const float4*)value, (float4*)cv, nbig4);
    cvt_tf32_kernel<<<nw4/256, 256>>>((const float4*)Wq, (float4*)wq, nw4);
    cvt_tf32_kernel<<<nw4/256, 256>>>((const float4*)Wk, (float4*)wk, nw4);
    cvt_tf32_kernel<<<nw4/256, 256>>>((const float4*)Wv, (float4*)wv, nw4);
    cvt_tf32_kernel<<<nw4/256, 256>>>((const float4*)Wo, (float4*)wo, nw4);

    dim3 gproj(DD / 128, SB / 128);
    tc_gemm<0><<<gproj, 256>>>(cq, wq, bq, qb);
    tc_gemm<0><<<gproj, 256>>>(ck, wk, bk, kb);
    tc_gemm<0><<<gproj, 256>>>(cv, wv, bv, vb);

    tc_gemm<1><<<dim3(SS/128, SS/128, BB), 256>>>(nullptr, nullptr, nullptr, nullptr);

    softmax_kernel<<<dim3(SS, BB), 256>>>();

    tc_gemm<2><<<dim3(DD/128, SS/128, BB), 256>>>(nullptr, nullptr, nullptr, nullptr);

    tc_gemm<3><<<gproj, 256>>>(xb, wo, bo, out);
}

// round 8
// speedup vs baseline: 7.7881x; 1.9196x over previous
#include <cuda_runtime.h>
#include <cuda_fp16.h>
#include <math.h>
#include <stdint.h>

#define SS 2048
#define BB 8
#define DD 1024
#define SB (SS*BB)
#define SCALE 0.03125f  /* 1/sqrt(1024) */

static __device__ __half g_q[(size_t)SB*DD];
static __device__ __half g_k[(size_t)SB*DD];
static __device__ __half g_v[(size_t)SB*DD];
static __device__ __half g_x[(size_t)SB*DD];
static __device__ float  g_p[(size_t)BB*SS*SS];   // fp32 scores
static __device__ __half g_ph[(size_t)BB*SS*SS];  // half probabilities
static __device__ __half g_cq[(size_t)SB*DD];
static __device__ __half g_ck[(size_t)SB*DD];
static __device__ __half g_cv[(size_t)SB*DD];
static __device__ __half g_wq[(size_t)DD*DD];
static __device__ __half g_wk[(size_t)DD*DD];
static __device__ __half g_wv[(size_t)DD*DD];
static __device__ __half g_wo[(size_t)DD*DD];

__device__ __forceinline__ void cpa16(uint32_t s, const void* g) {
    asm volatile("cp.async.cg.shared.global [%0], [%1], 16;" :: "r"(s), "l"(g));
}
#define CP_COMMIT() asm volatile("cp.async.commit_group;")
template<int N> __device__ __forceinline__ void cp_wait() {
    asm volatile("cp.async.wait_group %0;" :: "n"(N));
}

__device__ __forceinline__ void hmma16(float* c, const uint32_t* a, const uint32_t* b) {
    asm volatile(
        "mma.sync.aligned.m16n8k16.row.col.f32.f16.f16.f32 "
        "{%0,%1,%2,%3}, {%4,%5,%6,%7}, {%8,%9}, {%0,%1,%2,%3};"
        : "+f"(c[0]), "+f"(c[1]), "+f"(c[2]), "+f"(c[3])
        : "r"(a[0]), "r"(a[1]), "r"(a[2]), "r"(a[3]), "r"(b[0]), "r"(b[1]));
}
__device__ __forceinline__ void ldsm4(uint32_t& r0, uint32_t& r1, uint32_t& r2, uint32_t& r3, uint32_t addr) {
    asm volatile("ldmatrix.sync.aligned.m8n8.x4.shared.b16 {%0,%1,%2,%3}, [%4];"
                 : "=r"(r0), "=r"(r1), "=r"(r2), "=r"(r3) : "r"(addr));
}
__device__ __forceinline__ void ldsm4t(uint32_t& r0, uint32_t& r1, uint32_t& r2, uint32_t& r3, uint32_t addr) {
    asm volatile("ldmatrix.sync.aligned.m8n8.x4.trans.shared.b16 {%0,%1,%2,%3}, [%4];"
                 : "=r"(r0), "=r"(r1), "=r"(r2), "=r"(r3) : "r"(addr));
}

// ---------------------------------------------------------------------------
// fp16 NT GEMM: 128x128 CTA tile, BK=32 halves, 256 threads (8 warps 2x4),
// 3-stage cp.async pipeline + b16 ldmatrix. Rows are 64B (4 x 16B chunks),
// XOR-swizzled by ((row>>1)&3) -> conflict-free (same geometry as R2).
// MODE 0: C(half) = A @ W^T + bias   (Q/K/V projections)
// MODE 1: g_p(fp32) = SCALE * Qb @ Kb^T  (causal tile skip)
// MODE 3: C(fp32)  = A @ W^T + bias  (output projection -> d_out)
// ---------------------------------------------------------------------------
template<int MODE>
__global__ void __launch_bounds__(256, 2) hgemm_nt(
    const __half* __restrict__ Ag, const __half* __restrict__ Bg,
    const float* __restrict__ bias, void* __restrict__ Cg)
{
    const int bx = blockIdx.x, by = blockIdx.y, bz = blockIdx.z;
    if (MODE == 1 && bx > by) return;
    const int m0 = by * 128, n0 = bx * 128;

    const __half* A; const __half* Bp;
    int lda, ldb;
    if (MODE != 1) {
        A  = Ag + (size_t)m0 * DD;  lda = DD;
        Bp = Bg + (size_t)n0 * DD;  ldb = DD;
    } else {
        A  = g_q + (size_t)bz * DD + (size_t)m0 * (BB*DD);  lda = BB*DD;
        Bp = g_k + (size_t)bz * DD + (size_t)n0 * (BB*DD);  ldb = BB*DD;
    }
    const int KIT = DD / 32;

    extern __shared__ char dsm[];
    const uint32_t dsm_u = (uint32_t)__cvta_generic_to_shared(dsm);

    const int tid   = threadIdx.x;
    const int warp  = tid >> 5, lane = tid & 31;
    const int group = lane >> 2, quad = lane & 3;
    const int warp_m = (warp >> 2) * 64;
    const int warp_n = (warp & 3) * 32;
    const int sel = lane >> 3, lr = lane & 7;
    const int a_row  = warp_m + (sel & 1) * 8 + lr;   // + mi*16
    const int a_gsel = sel >> 1;
    const int a_sw   = (a_row >> 1) & 3;              // invariant under +16
    const int b_nrow = warp_n + (sel >> 1) * 8 + lr;  // + np*16
    const int b_gsel = sel & 1;
    const int b_sw   = (b_nrow >> 1) & 3;

    auto fill = [&](int s, int k0) {
        const uint32_t base = dsm_u + s * 16384;
        #pragma unroll
        for (int j = 0; j < 2; j++) {
            const int c = tid + 256 * j;        // 0..511 chunk id
            const int row = c >> 2, g = c & 3;
            const int phys = g ^ ((row >> 1) & 3);
            cpa16(base + row * 64 + phys * 16,        A  + (size_t)row * lda + k0 + g * 8);
            cpa16(base + 8192 + row * 64 + phys * 16, Bp + (size_t)row * ldb + k0 + g * 8);
        }
    };

    float acc[4][4][4];
    #pragma unroll
    for (int mi = 0; mi < 4; mi++)
        #pragma unroll
        for (int ni = 0; ni < 4; ni++)
            #pragma unroll
            for (int r = 0; r < 4; r++) acc[mi][ni][r] = 0.0f;

    auto compute = [&](int s) {
        const uint32_t aB = dsm_u + s * 16384;
        const uint32_t bB = aB + 8192;
        #pragma unroll
        for (int ks = 0; ks < 2; ks++) {
            uint32_t af[4][4];
            #pragma unroll
            for (int mi = 0; mi < 4; mi++) {
                const int row = a_row + mi * 16;
                const int phys = (ks * 2 + a_gsel) ^ a_sw;
                ldsm4(af[mi][0], af[mi][1], af[mi][2], af[mi][3],
                      aB + row * 64 + phys * 16);
            }
            uint32_t bf[4][2];
            #pragma unroll
            for (int np = 0; np < 2; np++) {
                const int nr = b_nrow + np * 16;
                const int phys = (ks * 2 + b_gsel) ^ b_sw;
                ldsm4(bf[np*2][0], bf[np*2][1], bf[np*2+1][0], bf[np*2+1][1],
                      bB + nr * 64 + phys * 16);
            }
            #pragma unroll
            for (int mi = 0; mi < 4; mi++)
                #pragma unroll
                for (int ni = 0; ni < 4; ni++)
                    hmma16(acc[mi][ni], af[mi], bf[ni]);
        }
    };

    fill(0, 0);  CP_COMMIT();
    fill(1, 32); CP_COMMIT();
    for (int it = 0; it < KIT; it++) {
        cp_wait<1>();
        __syncthreads();
        compute(it % 3);
        if (it + 2 < KIT) fill((it + 2) % 3, (it + 2) * 32);
        CP_COMMIT();
    }

    #pragma unroll
    for (int mi = 0; mi < 4; mi++) {
        const int mrow = m0 + warp_m + mi * 16 + group;
        #pragma unroll
        for (int ni = 0; ni < 4; ni++) {
            const int ncol = n0 + warp_n + ni * 8 + quad * 2;
            const float* c = acc[mi][ni];
            if (MODE == 0) {
                __half* C = (__half*)Cg;
                float2 bv = *(const float2*)(bias + ncol);
                *(__half2*)(C + (size_t)mrow * DD + ncol) =
                    __floats2half2_rn(c[0] + bv.x, c[1] + bv.y);
                *(__half2*)(C + (size_t)(mrow + 8) * DD + ncol) =
                    __floats2half2_rn(c[2] + bv.x, c[3] + bv.y);
            } else if (MODE == 1) {
                float* C = g_p + (size_t)bz * SS * SS;
                *(float2*)(C + (size_t)mrow * SS + ncol) =
                    make_float2(c[0] * SCALE, c[1] * SCALE);
                *(float2*)(C + (size_t)(mrow + 8) * SS + ncol) =
                    make_float2(c[2] * SCALE, c[3] * SCALE);
            } else {
                float* C = (float*)Cg;
                float2 bv = *(const float2*)(bias + ncol);
                *(float2*)(C + (size_t)mrow * DD + ncol) =
                    make_float2(c[0] + bv.x, c[1] + bv.y);
                *(float2*)(C + (size_t)(mrow + 8) * DD + ncol) =
                    make_float2(c[2] + bv.x, c[3] + bv.y);
            }
        }
    }
}

// ---------------------------------------------------------------------------
// fp16 PV GEMM: X(half) = P(half) @ Vb(half). 128x128 tile, BK=32.
// A = P (row-major, k contiguous) -> non-trans ldmatrix.
// B = V (k-major rows of 128 d-halves = 256B = 16 chunks, swizzle c^(k&7))
//     -> ldmatrix.x4.trans gives (k,n) fragments.
// K clipped at diagonal (m0+128); softmax zero-fills P above diagonal.
// ---------------------------------------------------------------------------
__global__ void __launch_bounds__(256, 2) pv_hgemm()
{
    const int bx = blockIdx.x, by = blockIdx.y, bz = blockIdx.z;
    const int m0 = by * 128, n0 = bx * 128;

    const __half* A  = g_ph + (size_t)bz * SS * SS + (size_t)m0 * SS;
    const __half* Vp = g_v + (size_t)bz * DD + n0;
    __half* C        = g_x + (size_t)bz * DD;
    const int lda = SS, ldv = BB*DD, ldc = BB*DD;
    const int KIT = (m0 + 128) / 32;

    extern __shared__ char dsm[];
    const uint32_t dsm_u = (uint32_t)__cvta_generic_to_shared(dsm);

    const int tid   = threadIdx.x;
    const int warp  = tid >> 5, lane = tid & 31;
    const int group = lane >> 2, quad = lane & 3;
    const int warp_m = (warp >> 2) * 64;
    const int warp_n = (warp & 3) * 32;
    const int sel = lane >> 3, lr = lane & 7;
    const int a_row  = warp_m + (sel & 1) * 8 + lr;
    const int a_gsel = sel >> 1;
    const int a_sw   = (a_row >> 1) & 3;
    // V trans-ldmatrix lane components: krow-within-16 and chunk offset
    const int v_klo  = (sel & 1) * 8 + lr;     // + ks*16
    const int v_goff = sel >> 1;               // chunk +0/+1

    auto fill = [&](int s, int k0) {
        const uint32_t base = dsm_u + s * 16384;
        #pragma unroll
        for (int j = 0; j < 2; j++) {
            const int c = tid + 256 * j;
            // A (P) tile: 128 rows x 64B
            const int row = c >> 2, g = c & 3;
            const int physA = g ^ ((row >> 1) & 3);
            cpa16(base + row * 64 + physA * 16, A + (size_t)row * lda + k0 + g * 8);
            // V tile: 32 k-rows x 256B (16 chunks)
            const int krow = c >> 4, cg = c & 15;
            const int physV = cg ^ (krow & 7);
            cpa16(base + 8192 + krow * 256 + physV * 16,
                  Vp + (size_t)(k0 + krow) * ldv + cg * 8);
        }
    };

    float acc[4][4][4];
    #pragma unroll
    for (int mi = 0; mi < 4; mi++)
        #pragma unroll
        for (int ni = 0; ni < 4; ni++)
            #pragma unroll
            for (int r = 0; r < 4; r++) acc[mi][ni][r] = 0.0f;

    auto compute = [&](int s) {
        const uint32_t aB = dsm_u + s * 16384;
        const uint32_t vB = aB + 8192;
        #pragma unroll
        for (int ks = 0; ks < 2; ks++) {
            uint32_t af[4][4];
            #pragma unroll
            for (int mi = 0; mi < 4; mi++) {
                const int row = a_row + mi * 16;
                const int phys = (ks * 2 + a_gsel) ^ a_sw;
                ldsm4(af[mi][0], af[mi][1], af[mi][2], af[mi][3],
                      aB + row * 64 + phys * 16);
            }
            uint32_t bf[4][2];
            const int krow = ks * 16 + v_klo;
            #pragma unroll
            for (int np = 0; np < 2; np++) {
                const int chunk = (warp_n >> 3) + np * 2 + v_goff;
                const int phys = chunk ^ (krow & 7);
                ldsm4t(bf[np*2][0], bf[np*2][1], bf[np*2+1][0], bf[np*2+1][1],
                       vB + krow * 256 + phys * 16);
            }
            #pragma unroll
            for (int mi = 0; mi < 4; mi++)
                #pragma unroll
                for (int ni = 0; ni < 4; ni++)
                    hmma16(acc[mi][ni], af[mi], bf[ni]);
        }
    };

    fill(0, 0);  CP_COMMIT();
    fill(1, 32); CP_COMMIT();
    for (int it = 0; it < KIT; it++) {
        cp_wait<1>();
        __syncthreads();
        compute(it % 3);
        if (it + 2 < KIT) fill((it + 2) % 3, (it + 2) * 32);
        CP_COMMIT();
    }

    #pragma unroll
    for (int mi = 0; mi < 4; mi++) {
        const int mrow = m0 + warp_m + mi * 16 + group;
        #pragma unroll
        for (int ni = 0; ni < 4; ni++) {
            const int ncol = n0 + warp_n + ni * 8 + quad * 2;
            const float* c = acc[mi][ni];
            *(__half2*)(C + (size_t)mrow * ldc + ncol) =
                __floats2half2_rn(c[0], c[1]);
            *(__half2*)(C + (size_t)(mrow + 8) * ldc + ncol) =
                __floats2half2_rn(c[2], c[3]);
        }
    }
}

// ---------------------------------------------------------------------------
// fp32 -> fp16 conversion copy
// ---------------------------------------------------------------------------
__global__ void __launch_bounds__(256) cvt_h_kernel(
    const float4* __restrict__ s, __half* __restrict__ d, int n4)
{
    int i = blockIdx.x * 256 + threadIdx.x;
    if (i < n4) {
        float4 v = s[i];
        __half2 h0 = __floats2half2_rn(v.x, v.y);
        __half2 h1 = __floats2half2_rn(v.z, v.w);
        *(uint2*)(d + (size_t)i * 4) = make_uint2(
            *(uint32_t*)&h0, *(uint32_t*)&h1);
    }
}

// ---------------------------------------------------------------------------
// Causal row softmax: reads fp32 scores g_p, writes half P to g_ph
// (zero-filled for j > i so PV can read full 128-row K blocks).
// ---------------------------------------------------------------------------
__global__ void __launch_bounds__(256) softmax_kernel()
{
    const int i = blockIdx.x, b = blockIdx.y;
    const float* rowp = g_p  + ((size_t)b * SS + i) * SS;
    __half* hrow      = g_ph + ((size_t)b * SS + i) * SS;
    const int len = i + 1;
    const int tid = threadIdx.x;

    __shared__ float red[32];

    float lmax = -INFINITY;
    for (int j = tid; j < len; j += 256) lmax = fmaxf(lmax, rowp[j]);
    #pragma unroll
    for (int o = 16; o > 0; o >>= 1)
        lmax = fmaxf(lmax, __shfl_xor_sync(0xffffffffu, lmax, o));
    if ((tid & 31) == 0) red[tid >> 5] = lmax;
    __syncthreads();
    if (tid < 32) {
        float v = (tid < 8) ? red[tid] : -INFINITY;
        #pragma unroll
        for (int o = 4; o > 0; o >>= 1)
            v = fmaxf(v, __shfl_xor_sync(0xffffffffu, v, o));
        if (tid == 0) red[0] = v;
    }
    __syncthreads();
    const float gmax = red[0];
    __syncthreads();

    float lsum = 0.0f;
    for (int j = tid; j < len; j += 256) lsum += expf(rowp[j] - gmax);
    #pragma unroll
    for (int o = 16; o > 0; o >>= 1)
        lsum += __shfl_xor_sync(0xffffffffu, lsum, o);
    if ((tid & 31) == 0) red[tid >> 5] = lsum;
    __syncthreads();
    if (tid < 32) {
        float v = (tid < 8) ? red[tid] : 0.0f;
        #pragma unroll
        for (int o = 4; o > 0; o >>= 1)
            v += __shfl_xor_sync(0xffffffffu, v, o);
        if (tid == 0) red[0] = v;
    }
    __syncthreads();
    const float inv = 1.0f / red[0];

    for (int j = tid; j < len; j += 256)
        hrow[j] = __float2half_rn(expf(rowp[j] - gmax) * inv);
    const __half hz = __float2half_rn(0.0f);
    for (int j = len + tid; j < SS; j += 256) hrow[j] = hz;
}

// ---------------------------------------------------------------------------
extern "C" void kernel_launch(void* const* d_in, const int* in_sizes, int n_in,
                              void* d_out, int out_size)
{
    const float* query = (const float*)d_in[0];
    const float* key   = (const float*)d_in[1];
    const float* value = (const float*)d_in[2];
    // d_in[3] = causal mask (structure known, not read)
    const float* Wq = (const float*)d_in[4];
    const float* bq = (const float*)d_in[5];
    const float* Wk = (const float*)d_in[6];
    const float* bk = (const float*)d_in[7];
    const float* Wv = (const float*)d_in[8];
    const float* bv = (const float*)d_in[9];
    const float* Wo = (const float*)d_in[10];
    const float* bo = (const float*)d_in[11];
    float* out = (float*)d_out;

    __half *qb, *kb, *vb, *xb, *cq, *ck, *cv, *wq, *wk, *wv, *wo;
    cudaGetSymbolAddress((void**)&qb, g_q);
    cudaGetSymbolAddress((void**)&kb, g_k);
    cudaGetSymbolAddress((void**)&vb, g_v);
    cudaGetSymbolAddress((void**)&xb, g_x);
    cudaGetSymbolAddress((void**)&cq, g_cq);
    cudaGetSymbolAddress((void**)&ck, g_ck);
    cudaGetSymbolAddress((void**)&cv, g_cv);
    cudaGetSymbolAddress((void**)&wq, g_wq);
    cudaGetSymbolAddress((void**)&wk, g_wk);
    cudaGetSymbolAddress((void**)&wv, g_wv);
    cudaGetSymbolAddress((void**)&wo, g_wo);

    const int SMEM = 49152;
    cudaFuncSetAttribute(hgemm_nt<0>, cudaFuncAttributeMaxDynamicSharedMemorySize, SMEM);
    cudaFuncSetAttribute(hgemm_nt<1>, cudaFuncAttributeMaxDynamicSharedMemorySize, SMEM);
    cudaFuncSetAttribute(hgemm_nt<3>, cudaFuncAttributeMaxDynamicSharedMemorySize, SMEM);
    cudaFuncSetAttribute(pv_hgemm,    cudaFuncAttributeMaxDynamicSharedMemorySize, SMEM);

    const int nbig4 = SB * DD / 4, nw4 = DD * DD / 4;
    cvt_h_kernel<<<nbig4/256, 256>>>((const float4*)query, cq, nbig4);
    cvt_h_kernel<<<nbig4/256, 256>>>((const float4*)key,   ck, nbig4);
    cvt_h_kernel<<<nbig4/256, 256>>>((const float4*)value, cv, nbig4);
    cvt_h_kernel<<<nw4/256, 256>>>((const float4*)Wq, wq, nw4);
    cvt_h_kernel<<<nw4/256, 256>>>((const float4*)Wk, wk, nw4);
    cvt_h_kernel<<<nw4/256, 256>>>((const float4*)Wv, wv, nw4);
    cvt_h_kernel<<<nw4/256, 256>>>((const float4*)Wo, wo, nw4);

    dim3 gproj(DD / 128, SB / 128);
    hgemm_nt<0><<<gproj, 256, SMEM>>>(cq, wq, bq, qb);
    hgemm_nt<0><<<gproj, 256, SMEM>>>(ck, wk, bk, kb);
    hgemm_nt<0><<<gproj, 256, SMEM>>>(cv, wv, bv, vb);

    hgemm_nt<1><<<dim3(SS/128, SS/128, BB), 256, SMEM>>>(nullptr, nullptr, nullptr, nullptr);

    softmax_kernel<<<dim3(SS, BB), 256>>>();

    pv_hgemm<<<dim3(DD/128, SS/128, BB), 256, SMEM>>>();

    hgemm_nt<3><<<gproj, 256, SMEM>>>(xb, wo, bo, out);
}

// round 12
// speedup vs baseline: 8.2506x; 1.0594x over previous
#include <cuda_runtime.h>
#include <cuda_fp16.h>
#include <math.h>
#include <stdint.h>

#define SS 2048
#define BB 8
#define DD 1024
#define SB (SS*BB)
#define SCALE 0.03125f  /* 1/sqrt(1024) */

static __device__ __half g_q[(size_t)SB*DD];
static __device__ __half g_k[(size_t)SB*DD];
static __device__ __half g_v[(size_t)SB*DD];
static __device__ __half g_x[(size_t)SB*DD];
static __device__ __half g_ph[(size_t)BB*SS*SS];       // half exp(scores), unnormalized
static __device__ float  g_psum[(size_t)BB*16*4*SS];   // [b][jt][wn][row] partial row sums
static __device__ __half g_cq[(size_t)SB*DD];
static __device__ __half g_ck[(size_t)SB*DD];
static __device__ __half g_cv[(size_t)SB*DD];
static __device__ __half g_wq[(size_t)DD*DD];
static __device__ __half g_wk[(size_t)DD*DD];
static __device__ __half g_wv[(size_t)DD*DD];
static __device__ __half g_wo[(size_t)DD*DD];

__device__ __forceinline__ void cpa16(uint32_t s, const void* g) {
    asm volatile("cp.async.cg.shared.global [%0], [%1], 16;" :: "r"(s), "l"(g));
}
#define CP_COMMIT() asm volatile("cp.async.commit_group;")
template<int N> __device__ __forceinline__ void cp_wait() {
    asm volatile("cp.async.wait_group %0;" :: "n"(N));
}

__device__ __forceinline__ void hmma16(float* c, const uint32_t* a, const uint32_t* b) {
    asm volatile(
        "mma.sync.aligned.m16n8k16.row.col.f32.f16.f16.f32 "
        "{%0,%1,%2,%3}, {%4,%5,%6,%7}, {%8,%9}, {%0,%1,%2,%3};"
        : "+f"(c[0]), "+f"(c[1]), "+f"(c[2]), "+f"(c[3])
        : "r"(a[0]), "r"(a[1]), "r"(a[2]), "r"(a[3]), "r"(b[0]), "r"(b[1]));
}
__device__ __forceinline__ void ldsm4(uint32_t& r0, uint32_t& r1, uint32_t& r2, uint32_t& r3, uint32_t addr) {
    asm volatile("ldmatrix.sync.aligned.m8n8.x4.shared.b16 {%0,%1,%2,%3}, [%4];"
                 : "=r"(r0), "=r"(r1), "=r"(r2), "=r"(r3) : "r"(addr));
}
__device__ __forceinline__ void ldsm4t(uint32_t& r0, uint32_t& r1, uint32_t& r2, uint32_t& r3, uint32_t addr) {
    asm volatile("ldmatrix.sync.aligned.m8n8.x4.trans.shared.b16 {%0,%1,%2,%3}, [%4];"
                 : "=r"(r0), "=r"(r1), "=r"(r2), "=r"(r3) : "r"(addr));
}

// ---------------------------------------------------------------------------
// fp16 NT GEMM: 128x128 CTA tile, BK=32, 256 threads (8 warps 2x4),
// 3-stage cp.async pipeline + b16 ldmatrix.
// MODE 0: C(half) = A @ W^T + bias          (Q/K/V projections)
// MODE 1: g_ph(half) = exp(SCALE * Qb@Kb^T) masked causal; row partials
//         to g_psum (no softmax kernel; normalization deferred to PV)
// MODE 3: C(fp32) = A @ W^T + bias          (output projection -> d_out)
// ---------------------------------------------------------------------------
template<int MODE>
__global__ void __launch_bounds__(256, 2) hgemm_nt(
    const __half* __restrict__ Ag, const __half* __restrict__ Bg,
    const float* __restrict__ bias, void* __restrict__ Cg)
{
    const int bx = blockIdx.x, by = blockIdx.y, bz = blockIdx.z;
    if (MODE == 1 && bx > by) return;
    const int m0 = by * 128, n0 = bx * 128;

    const __half* A; const __half* Bp;
    int lda, ldb;
    if (MODE != 1) {
        A  = Ag + (size_t)m0 * DD;  lda = DD;
        Bp = Bg + (size_t)n0 * DD;  ldb = DD;
    } else {
        A  = g_q + (size_t)bz * DD + (size_t)m0 * (BB*DD);  lda = BB*DD;
        Bp = g_k + (size_t)bz * DD + (size_t)n0 * (BB*DD);  ldb = BB*DD;
    }
    const int KIT = DD / 32;

    extern __shared__ char dsm[];
    const uint32_t dsm_u = (uint32_t)__cvta_generic_to_shared(dsm);

    const int tid   = threadIdx.x;
    const int warp  = tid >> 5, lane = tid & 31;
    const int group = lane >> 2, quad = lane & 3;
    const int warp_m = (warp >> 2) * 64;
    const int warp_n = (warp & 3) * 32;
    const int sel = lane >> 3, lr = lane & 7;
    const int a_row  = warp_m + (sel & 1) * 8 + lr;
    const int a_gsel = sel >> 1;
    const int a_sw   = (a_row >> 1) & 3;
    const int b_nrow = warp_n + (sel >> 1) * 8 + lr;
    const int b_gsel = sel & 1;
    const int b_sw   = (b_nrow >> 1) & 3;

    auto fill = [&](int s, int k0) {
        const uint32_t base = dsm_u + s * 16384;
        #pragma unroll
        for (int j = 0; j < 2; j++) {
            const int c = tid + 256 * j;
            const int row = c >> 2, g = c & 3;
            const int phys = g ^ ((row >> 1) & 3);
            cpa16(base + row * 64 + phys * 16,        A  + (size_t)row * lda + k0 + g * 8);
            cpa16(base + 8192 + row * 64 + phys * 16, Bp + (size_t)row * ldb + k0 + g * 8);
        }
    };

    float acc[4][4][4];
    #pragma unroll
    for (int mi = 0; mi < 4; mi++)
        #pragma unroll
        for (int ni = 0; ni < 4; ni++)
            #pragma unroll
            for (int r = 0; r < 4; r++) acc[mi][ni][r] = 0.0f;

    auto compute = [&](int s) {
        const uint32_t aB = dsm_u + s * 16384;
        const uint32_t bB = aB + 8192;
        #pragma unroll
        for (int ks = 0; ks < 2; ks++) {
            uint32_t af[4][4];
            #pragma unroll
            for (int mi = 0; mi < 4; mi++) {
                const int row = a_row + mi * 16;
                const int phys = (ks * 2 + a_gsel) ^ a_sw;
                ldsm4(af[mi][0], af[mi][1], af[mi][2], af[mi][3],
                      aB + row * 64 + phys * 16);
            }
            uint32_t bf[4][2];
            #pragma unroll
            for (int np = 0; np < 2; np++) {
                const int nr = b_nrow + np * 16;
                const int phys = (ks * 2 + b_gsel) ^ b_sw;
                ldsm4(bf[np*2][0], bf[np*2][1], bf[np*2+1][0], bf[np*2+1][1],
                      bB + nr * 64 + phys * 16);
            }
            #pragma unroll
            for (int mi = 0; mi < 4; mi++)
                #pragma unroll
                for (int ni = 0; ni < 4; ni++)
                    hmma16(acc[mi][ni], af[mi], bf[ni]);
        }
    };

    fill(0, 0);  CP_COMMIT();
    fill(1, 32); CP_COMMIT();
    for (int it = 0; it < KIT; it++) {
        cp_wait<1>();
        __syncthreads();
        compute(it % 3);
        if (it + 2 < KIT) fill((it + 2) % 3, (it + 2) * 32);
        CP_COMMIT();
    }

    if (MODE == 1) {
        // exp epilogue: write unnormalized half P', accumulate row partials
        __half* C = g_ph + (size_t)bz * SS * SS;
        float* psum = g_psum + (((size_t)bz * 16 + bx) * 4 + (warp & 3)) * SS;
        #pragma unroll
        for (int mi = 0; mi < 4; mi++) {
            const int r0 = m0 + warp_m + mi * 16 + group;
            const int r1 = r0 + 8;
            float s0 = 0.0f, s1 = 0.0f;
            #pragma unroll
            for (int ni = 0; ni < 4; ni++) {
                const int ncol = n0 + warp_n + ni * 8 + quad * 2;
                const float* c = acc[mi][ni];
                float p0 = (ncol     <= r0) ? expf(c[0] * SCALE) : 0.0f;
                float p1 = (ncol + 1 <= r0) ? expf(c[1] * SCALE) : 0.0f;
                float p2 = (ncol     <= r1) ? expf(c[2] * SCALE) : 0.0f;
                float p3 = (ncol + 1 <= r1) ? expf(c[3] * SCALE) : 0.0f;
                s0 += p0 + p1;
                s1 += p2 + p3;
                *(__half2*)(C + (size_t)r0 * SS + ncol) = __floats2half2_rn(p0, p1);
                *(__half2*)(C + (size_t)r1 * SS + ncol) = __floats2half2_rn(p2, p3);
            }
            s0 += __shfl_xor_sync(0xffffffffu, s0, 1);
            s0 += __shfl_xor_sync(0xffffffffu, s0, 2);
            s1 += __shfl_xor_sync(0xffffffffu, s1, 1);
            s1 += __shfl_xor_sync(0xffffffffu, s1, 2);
            if (quad == 0) { psum[r0] = s0; psum[r1] = s1; }
        }
    } else {
        #pragma unroll
        for (int mi = 0; mi < 4; mi++) {
            const int mrow = m0 + warp_m + mi * 16 + group;
            #pragma unroll
            for (int ni = 0; ni < 4; ni++) {
                const int ncol = n0 + warp_n + ni * 8 + quad * 2;
                const float* c = acc[mi][ni];
                if (MODE == 0) {
                    __half* C = (__half*)Cg;
                    float2 bv = *(const float2*)(bias + ncol);
                    *(__half2*)(C + (size_t)mrow * DD + ncol) =
                        __floats2half2_rn(c[0] + bv.x, c[1] + bv.y);
                    *(__half2*)(C + (size_t)(mrow + 8) * DD + ncol) =
                        __floats2half2_rn(c[2] + bv.x, c[3] + bv.y);
                } else {
                    float* C = (float*)Cg;
                    float2 bv = *(const float2*)(bias + ncol);
                    *(float2*)(C + (size_t)mrow * DD + ncol) =
                        make_float2(c[0] + bv.x, c[1] + bv.y);
                    *(float2*)(C + (size_t)(mrow + 8) * DD + ncol) =
                        make_float2(c[2] + bv.x, c[3] + bv.y);
                }
            }
        }
    }
}

// ---------------------------------------------------------------------------
// fp16 PV GEMM: X(half) = diag(1/rowsum) * (P' @ Vb). 128x128 tile, BK=32.
// Row sums assembled from g_psum partials (deterministic, no atomics).
// ---------------------------------------------------------------------------
__global__ void __launch_bounds__(256, 2) pv_hgemm()
{
    const int bx = blockIdx.x, by = blockIdx.y, bz = blockIdx.z;
    const int m0 = by * 128, n0 = bx * 128;

    const __half* A  = g_ph + (size_t)bz * SS * SS + (size_t)m0 * SS;
    const __half* Vp = g_v + (size_t)bz * DD + n0;
    __half* C        = g_x + (size_t)bz * DD;
    const int lda = SS, ldv = BB*DD, ldc = BB*DD;
    const int KIT = (m0 + 128) / 32;

    extern __shared__ char dsm[];
    const uint32_t dsm_u = (uint32_t)__cvta_generic_to_shared(dsm);
    __shared__ float sinv[128];

    const int tid   = threadIdx.x;
    const int warp  = tid >> 5, lane = tid & 31;
    const int group = lane >> 2, quad = lane & 3;
    const int warp_m = (warp >> 2) * 64;
    const int warp_n = (warp & 3) * 32;
    const int sel = lane >> 3, lr = lane & 7;
    const int a_row  = warp_m + (sel & 1) * 8 + lr;
    const int a_gsel = sel >> 1;
    const int a_sw   = (a_row >> 1) & 3;
    const int v_klo  = (sel & 1) * 8 + lr;
    const int v_goff = sel >> 1;

    // assemble row normalizers from partial sums
    if (tid < 128) {
        float s = 0.0f;
        const int row = m0 + tid;
        for (int jt = 0; jt <= by; jt++) {
            const float* p = g_psum + (((size_t)bz * 16 + jt) * 4) * SS + row;
            s += p[0] + p[SS] + p[2*SS] + p[3*SS];
        }
        sinv[tid] = 1.0f / s;
    }

    auto fill = [&](int s, int k0) {
        const uint32_t base = dsm_u + s * 16384;
        #pragma unroll
        for (int j = 0; j < 2; j++) {
            const int c = tid + 256 * j;
            const int row = c >> 2, g = c & 3;
            const int physA = g ^ ((row >> 1) & 3);
            cpa16(base + row * 64 + physA * 16, A + (size_t)row * lda + k0 + g * 8);
            const int krow = c >> 4, cg = c & 15;
            const int physV = cg ^ (krow & 7);
            cpa16(base + 8192 + krow * 256 + physV * 16,
                  Vp + (size_t)(k0 + krow) * ldv + cg * 8);
        }
    };

    float acc[4][4][4];
    #pragma unroll
    for (int mi = 0; mi < 4; mi++)
        #pragma unroll
        for (int ni = 0; ni < 4; ni++)
            #pragma unroll
            for (int r = 0; r < 4; r++) acc[mi][ni][r] = 0.0f;

    auto compute = [&](int s) {
        const uint32_t aB = dsm_u + s * 16384;
        const uint32_t vB = aB + 8192;
        #pragma unroll
        for (int ks = 0; ks < 2; ks++) {
            uint32_t af[4][4];
            #pragma unroll
            for (int mi = 0; mi < 4; mi++) {
                const int row = a_row + mi * 16;
                const int phys = (ks * 2 + a_gsel) ^ a_sw;
                ldsm4(af[mi][0], af[mi][1], af[mi][2], af[mi][3],
                      aB + row * 64 + phys * 16);
            }
            uint32_t bf[4][2];
            const int krow = ks * 16 + v_klo;
            #pragma unroll
            for (int np = 0; np < 2; np++) {
                const int chunk = (warp_n >> 3) + np * 2 + v_goff;
                const int phys = chunk ^ (krow & 7);
                ldsm4t(bf[np*2][0], bf[np*2][1], bf[np*2+1][0], bf[np*2+1][1],
                       vB + krow * 256 + phys * 16);
            }
            #pragma unroll
            for (int mi = 0; mi < 4; mi++)
                #pragma unroll
                for (int ni = 0; ni < 4; ni++)
                    hmma16(acc[mi][ni], af[mi], bf[ni]);
        }
    };

    fill(0, 0);  CP_COMMIT();
    fill(1, 32); CP_COMMIT();
    for (int it = 0; it < KIT; it++) {
        cp_wait<1>();
        __syncthreads();
        compute(it % 3);
        if (it + 2 < KIT) fill((it + 2) % 3, (it + 2) * 32);
        CP_COMMIT();
    }

    #pragma unroll
    for (int mi = 0; mi < 4; mi++) {
        const int mrow = m0 + warp_m + mi * 16 + group;
        const float inv0 = sinv[mrow - m0];
        const float inv1 = sinv[mrow + 8 - m0];
        #pragma unroll
        for (int ni = 0; ni < 4; ni++) {
            const int ncol = n0 + warp_n + ni * 8 + quad * 2;
            const float* c = acc[mi][ni];
            *(__half2*)(C + (size_t)mrow * ldc + ncol) =
                __floats2half2_rn(c[0] * inv0, c[1] * inv0);
            *(__half2*)(C + (size_t)(mrow + 8) * ldc + ncol) =
                __floats2half2_rn(c[2] * inv1, c[3] * inv1);
        }
    }
}

// ---------------------------------------------------------------------------
__global__ void __launch_bounds__(256) cvt_h_kernel(
    const float4* __restrict__ s, __half* __restrict__ d, int n4)
{
    int i = blockIdx.x * 256 + threadIdx.x;
    if (i < n4) {
        float4 v = s[i];
        __half2 h0 = __floats2half2_rn(v.x, v.y);
        __half2 h1 = __floats2half2_rn(v.z, v.w);
        *(uint2*)(d + (size_t)i * 4) = make_uint2(
            *(uint32_t*)&h0, *(uint32_t*)&h1);
    }
}

// ---------------------------------------------------------------------------
extern "C" void kernel_launch(void* const* d_in, const int* in_sizes, int n_in,
                              void* d_out, int out_size)
{
    const float* query = (const float*)d_in[0];
    const float* key   = (const float*)d_in[1];
    const float* value = (const float*)d_in[2];
    // d_in[3] = causal mask (structure known, not read)
    const float* Wq = (const float*)d_in[4];
    const float* bq = (const float*)d_in[5];
    const float* Wk = (const float*)d_in[6];
    const float* bk = (const float*)d_in[7];
    const float* Wv = (const float*)d_in[8];
    const float* bv = (const float*)d_in[9];
    const float* Wo = (const float*)d_in[10];
    const float* bo = (const float*)d_in[11];
    float* out = (float*)d_out;

    __half *qb, *kb, *vb, *xb, *cq, *ck, *cv, *wq, *wk, *wv, *wo;
    cudaGetSymbolAddress((void**)&qb, g_q);
    cudaGetSymbolAddress((void**)&kb, g_k);
    cudaGetSymbolAddress((void**)&vb, g_v);
    cudaGetSymbolAddress((void**)&xb, g_x);
    cudaGetSymbolAddress((void**)&cq, g_cq);
    cudaGetSymbolAddress((void**)&ck, g_ck);
    cudaGetSymbolAddress((void**)&cv, g_cv);
    cudaGetSymbolAddress((void**)&wq, g_wq);
    cudaGetSymbolAddress((void**)&wk, g_wk);
    cudaGetSymbolAddress((void**)&wv, g_wv);
    cudaGetSymbolAddress((void**)&wo, g_wo);

    const int SMEM = 49152;
    cudaFuncSetAttribute(hgemm_nt<0>, cudaFuncAttributeMaxDynamicSharedMemorySize, SMEM);
    cudaFuncSetAttribute(hgemm_nt<1>, cudaFuncAttributeMaxDynamicSharedMemorySize, SMEM);
    cudaFuncSetAttribute(hgemm_nt<3>, cudaFuncAttributeMaxDynamicSharedMemorySize, SMEM);
    cudaFuncSetAttribute(pv_hgemm,    cudaFuncAttributeMaxDynamicSharedMemorySize, SMEM);

    const int nbig4 = SB * DD / 4, nw4 = DD * DD / 4;
    cvt_h_kernel<<<nbig4/256, 256>>>((const float4*)query, cq, nbig4);
    cvt_h_kernel<<<nbig4/256, 256>>>((const float4*)key,   ck, nbig4);
    cvt_h_kernel<<<nbig4/256, 256>>>((const float4*)value, cv, nbig4);
    cvt_h_kernel<<<nw4/256, 256>>>((const float4*)Wq, wq, nw4);
    cvt_h_kernel<<<nw4/256, 256>>>((const float4*)Wk, wk, nw4);
    cvt_h_kernel<<<nw4/256, 256>>>((const float4*)Wv, wv, nw4);
    cvt_h_kernel<<<nw4/256, 256>>>((const float4*)Wo, wo, nw4);

    dim3 gproj(DD / 128, SB / 128);
    hgemm_nt<0><<<gproj, 256, SMEM>>>(cq, wq, bq, qb);
    hgemm_nt<0><<<gproj, 256, SMEM>>>(ck, wk, bk, kb);
    hgemm_nt<0><<<gproj, 256, SMEM>>>(cv, wv, bv, vb);

    hgemm_nt<1><<<dim3(SS/128, SS/128, BB), 256, SMEM>>>(nullptr, nullptr, nullptr, nullptr);

    pv_hgemm<<<dim3(DD/128, SS/128, BB), 256, SMEM>>>();

    hgemm_nt<3><<<gproj, 256, SMEM>>>(xb, wo, bo, out);
}

// round 13
// speedup vs baseline: 8.4751x; 1.0272x over previous
#include <cuda_runtime.h>
#include <cuda_fp16.h>
#include <math.h>
#include <stdint.h>

#define SS 2048
#define BB 8
#define DD 1024
#define SB (SS*BB)
#define SCALE 0.03125f  /* 1/sqrt(1024) */

static __device__ __half g_q[(size_t)SB*DD];
static __device__ __half g_k[(size_t)SB*DD];
static __device__ __half g_v[(size_t)SB*DD];
static __device__ __half g_x[(size_t)SB*DD];
static __device__ __half g_ph[(size_t)BB*SS*SS];       // half exp(scores), unnormalized
static __device__ float  g_psum[(size_t)BB*16*4*SS];   // [b][jt][wn][row] partial row sums
static __device__ __half g_cq[(size_t)SB*DD];
static __device__ __half g_ck[(size_t)SB*DD];
static __device__ __half g_cv[(size_t)SB*DD];
static __device__ __half g_wq[(size_t)DD*DD];
static __device__ __half g_wk[(size_t)DD*DD];
static __device__ __half g_wv[(size_t)DD*DD];
static __device__ __half g_wo[(size_t)DD*DD];

__device__ __forceinline__ void cpa16(uint32_t s, const void* g) {
    asm volatile("cp.async.cg.shared.global [%0], [%1], 16;" :: "r"(s), "l"(g));
}
#define CP_COMMIT() asm volatile("cp.async.commit_group;")
template<int N> __device__ __forceinline__ void cp_wait() {
    asm volatile("cp.async.wait_group %0;" :: "n"(N));
}

__device__ __forceinline__ void hmma16(float* c, const uint32_t* a, const uint32_t* b) {
    asm volatile(
        "mma.sync.aligned.m16n8k16.row.col.f32.f16.f16.f32 "
        "{%0,%1,%2,%3}, {%4,%5,%6,%7}, {%8,%9}, {%0,%1,%2,%3};"
        : "+f"(c[0]), "+f"(c[1]), "+f"(c[2]), "+f"(c[3])
        : "r"(a[0]), "r"(a[1]), "r"(a[2]), "r"(a[3]), "r"(b[0]), "r"(b[1]));
}
__device__ __forceinline__ void ldsm4(uint32_t& r0, uint32_t& r1, uint32_t& r2, uint32_t& r3, uint32_t addr) {
    asm volatile("ldmatrix.sync.aligned.m8n8.x4.shared.b16 {%0,%1,%2,%3}, [%4];"
                 : "=r"(r0), "=r"(r1), "=r"(r2), "=r"(r3) : "r"(addr));
}
__device__ __forceinline__ void ldsm4t(uint32_t& r0, uint32_t& r1, uint32_t& r2, uint32_t& r3, uint32_t addr) {
    asm volatile("ldmatrix.sync.aligned.m8n8.x4.trans.shared.b16 {%0,%1,%2,%3}, [%4];"
                 : "=r"(r0), "=r"(r1), "=r"(r2), "=r"(r3) : "r"(addr));
}

// ===========================================================================
// Shared GEMM machinery (identical to verified R11 hot loop)
// ===========================================================================
struct GemmCtx {
    uint32_t dsm_u;
    int tid, warp, lane, group, quad;
    int warp_m, warp_n;
    int a_row, a_gsel, a_sw;
    int b_nrow, b_gsel, b_sw;
};
__device__ __forceinline__ void init_ctx(GemmCtx& g, uint32_t dsm_u) {
    g.dsm_u = dsm_u;
    g.tid = threadIdx.x;
    g.warp = g.tid >> 5; g.lane = g.tid & 31;
    g.group = g.lane >> 2; g.quad = g.lane & 3;
    g.warp_m = (g.warp >> 2) * 64;
    g.warp_n = (g.warp & 3) * 32;
    const int sel = g.lane >> 3, lr = g.lane & 7;
    g.a_row  = g.warp_m + (sel & 1) * 8 + lr;
    g.a_gsel = sel >> 1;
    g.a_sw   = (g.a_row >> 1) & 3;
    g.b_nrow = g.warp_n + (sel >> 1) * 8 + lr;
    g.b_gsel = sel & 1;
    g.b_sw   = (g.b_nrow >> 1) & 3;
}
__device__ __forceinline__ void nt_fill(const GemmCtx& g, int s, int k0,
                                        const __half* A, int lda,
                                        const __half* Bp, int ldb) {
    const uint32_t base = g.dsm_u + s * 16384;
    #pragma unroll
    for (int j = 0; j < 2; j++) {
        const int c = g.tid + 256 * j;
        const int row = c >> 2, gg = c & 3;
        const int phys = gg ^ ((row >> 1) & 3);
        cpa16(base + row * 64 + phys * 16,        A  + (size_t)row * lda + k0 + gg * 8);
        cpa16(base + 8192 + row * 64 + phys * 16, Bp + (size_t)row * ldb + k0 + gg * 8);
    }
}
__device__ __forceinline__ void nt_compute(const GemmCtx& g, int s, float acc[4][4][4]) {
    const uint32_t aB = g.dsm_u + s * 16384;
    const uint32_t bB = aB + 8192;
    #pragma unroll
    for (int ks = 0; ks < 2; ks++) {
        uint32_t af[4][4];
        #pragma unroll
        for (int mi = 0; mi < 4; mi++) {
            const int row = g.a_row + mi * 16;
            const int phys = (ks * 2 + g.a_gsel) ^ g.a_sw;
            ldsm4(af[mi][0], af[mi][1], af[mi][2], af[mi][3],
                  aB + row * 64 + phys * 16);
        }
        uint32_t bf[4][2];
        #pragma unroll
        for (int np = 0; np < 2; np++) {
            const int nr = g.b_nrow + np * 16;
            const int phys = (ks * 2 + g.b_gsel) ^ g.b_sw;
            ldsm4(bf[np*2][0], bf[np*2][1], bf[np*2+1][0], bf[np*2+1][1],
                  bB + nr * 64 + phys * 16);
        }
        #pragma unroll
        for (int mi = 0; mi < 4; mi++)
            #pragma unroll
            for (int ni = 0; ni < 4; ni++)
                hmma16(acc[mi][ni], af[mi], bf[ni]);
    }
}
#define ZERO_ACC(acc) \
    _Pragma("unroll") for (int mi = 0; mi < 4; mi++) \
        _Pragma("unroll") for (int ni = 0; ni < 4; ni++) \
            _Pragma("unroll") for (int r = 0; r < 4; r++) acc[mi][ni][r] = 0.0f;

// ---------------------------------------------------------------------------
// Batched QKV projection: z selects (input, weight, bias, output).
// C(half) = A @ W^T + bias.  One launch, three projections.
// ---------------------------------------------------------------------------
__global__ void __launch_bounds__(256, 2) hgemm_qkv(
    const __half* __restrict__ A0, const __half* __restrict__ A1, const __half* __restrict__ A2,
    const float* __restrict__ b0, const float* __restrict__ b1, const float* __restrict__ b2)
{
    const int bx = blockIdx.x, by = blockIdx.y, bz = blockIdx.z;
    const int m0 = by * 128, n0 = bx * 128;

    const __half* Ag = (bz == 0) ? A0 : (bz == 1) ? A1 : A2;
    const __half* Wg = (bz == 0) ? g_wq : (bz == 1) ? g_wk : g_wv;
    const float*  bias = (bz == 0) ? b0 : (bz == 1) ? b1 : b2;
    __half* Cg = (bz == 0) ? g_q : (bz == 1) ? g_k : g_v;

    const __half* A  = Ag + (size_t)m0 * DD;
    const __half* Bp = Wg + (size_t)n0 * DD;
    const int KIT = DD / 32;

    extern __shared__ char dsm[];
    GemmCtx g; init_ctx(g, (uint32_t)__cvta_generic_to_shared(dsm));

    float acc[4][4][4];
    ZERO_ACC(acc)

    nt_fill(g, 0, 0, A, DD, Bp, DD);  CP_COMMIT();
    nt_fill(g, 1, 32, A, DD, Bp, DD); CP_COMMIT();
    for (int it = 0; it < KIT; it++) {
        cp_wait<1>();
        __syncthreads();
        nt_compute(g, it % 3, acc);
        if (it + 2 < KIT) nt_fill(g, (it + 2) % 3, (it + 2) * 32, A, DD, Bp, DD);
        CP_COMMIT();
    }

    #pragma unroll
    for (int mi = 0; mi < 4; mi++) {
        const int mrow = m0 + g.warp_m + mi * 16 + g.group;
        #pragma unroll
        for (int ni = 0; ni < 4; ni++) {
            const int ncol = n0 + g.warp_n + ni * 8 + g.quad * 2;
            const float* c = acc[mi][ni];
            float2 bv = *(const float2*)(bias + ncol);
            *(__half2*)(Cg + (size_t)mrow * DD + ncol) =
                __floats2half2_rn(c[0] + bv.x, c[1] + bv.y);
            *(__half2*)(Cg + (size_t)(mrow + 8) * DD + ncol) =
                __floats2half2_rn(c[2] + bv.x, c[3] + bv.y);
        }
    }
}

// ---------------------------------------------------------------------------
// Scores: g_ph(half) = exp(SCALE * Qb@Kb^T) masked causal, psum partials.
// ---------------------------------------------------------------------------
__global__ void __launch_bounds__(256, 2) hgemm_scores()
{
    const int bx = blockIdx.x, by = blockIdx.y, bz = blockIdx.z;
    if (bx > by) return;
    const int m0 = by * 128, n0 = bx * 128;

    const __half* A  = g_q + (size_t)bz * DD + (size_t)m0 * (BB*DD);
    const __half* Bp = g_k + (size_t)bz * DD + (size_t)n0 * (BB*DD);
    const int KIT = DD / 32;

    extern __shared__ char dsm[];
    GemmCtx g; init_ctx(g, (uint32_t)__cvta_generic_to_shared(dsm));

    float acc[4][4][4];
    ZERO_ACC(acc)

    nt_fill(g, 0, 0, A, BB*DD, Bp, BB*DD);  CP_COMMIT();
    nt_fill(g, 1, 32, A, BB*DD, Bp, BB*DD); CP_COMMIT();
    for (int it = 0; it < KIT; it++) {
        cp_wait<1>();
        __syncthreads();
        nt_compute(g, it % 3, acc);
        if (it + 2 < KIT) nt_fill(g, (it + 2) % 3, (it + 2) * 32, A, BB*DD, Bp, BB*DD);
        CP_COMMIT();
    }

    __half* C = g_ph + (size_t)bz * SS * SS;
    float* psum = g_psum + (((size_t)bz * 16 + bx) * 4 + (g.warp & 3)) * SS;
    #pragma unroll
    for (int mi = 0; mi < 4; mi++) {
        const int r0 = m0 + g.warp_m + mi * 16 + g.group;
        const int r1 = r0 + 8;
        float s0 = 0.0f, s1 = 0.0f;
        #pragma unroll
        for (int ni = 0; ni < 4; ni++) {
            const int ncol = n0 + g.warp_n + ni * 8 + g.quad * 2;
            const float* c = acc[mi][ni];
            float p0 = (ncol     <= r0) ? expf(c[0] * SCALE) : 0.0f;
            float p1 = (ncol + 1 <= r0) ? expf(c[1] * SCALE) : 0.0f;
            float p2 = (ncol     <= r1) ? expf(c[2] * SCALE) : 0.0f;
            float p3 = (ncol + 1 <= r1) ? expf(c[3] * SCALE) : 0.0f;
            s0 += p0 + p1;
            s1 += p2 + p3;
            *(__half2*)(C + (size_t)r0 * SS + ncol) = __floats2half2_rn(p0, p1);
            *(__half2*)(C + (size_t)r1 * SS + ncol) = __floats2half2_rn(p2, p3);
        }
        s0 += __shfl_xor_sync(0xffffffffu, s0, 1);
        s0 += __shfl_xor_sync(0xffffffffu, s0, 2);
        s1 += __shfl_xor_sync(0xffffffffu, s1, 1);
        s1 += __shfl_xor_sync(0xffffffffu, s1, 2);
        if (g.quad == 0) { psum[r0] = s0; psum[r1] = s1; }
    }
}

// ---------------------------------------------------------------------------
// Output projection: C(fp32) = A @ W^T + bias -> d_out
// ---------------------------------------------------------------------------
__global__ void __launch_bounds__(256, 2) hgemm_oproj(
    const float* __restrict__ bias, float* __restrict__ Cg)
{
    const int bx = blockIdx.x, by = blockIdx.y;
    const int m0 = by * 128, n0 = bx * 128;

    const __half* A  = g_x + (size_t)m0 * DD;
    const __half* Bp = g_wo + (size_t)n0 * DD;
    const int KIT = DD / 32;

    extern __shared__ char dsm[];
    GemmCtx g; init_ctx(g, (uint32_t)__cvta_generic_to_shared(dsm));

    float acc[4][4][4];
    ZERO_ACC(acc)

    nt_fill(g, 0, 0, A, DD, Bp, DD);  CP_COMMIT();
    nt_fill(g, 1, 32, A, DD, Bp, DD); CP_COMMIT();
    for (int it = 0; it < KIT; it++) {
        cp_wait<1>();
        __syncthreads();
        nt_compute(g, it % 3, acc);
        if (it + 2 < KIT) nt_fill(g, (it + 2) % 3, (it + 2) * 32, A, DD, Bp, DD);
        CP_COMMIT();
    }

    #pragma unroll
    for (int mi = 0; mi < 4; mi++) {
        const int mrow = m0 + g.warp_m + mi * 16 + g.group;
        #pragma unroll
        for (int ni = 0; ni < 4; ni++) {
            const int ncol = n0 + g.warp_n + ni * 8 + g.quad * 2;
            const float* c = acc[mi][ni];
            float2 bv = *(const float2*)(bias + ncol);
            *(float2*)(Cg + (size_t)mrow * DD + ncol) =
                make_float2(c[0] + bv.x, c[1] + bv.y);
            *(float2*)(Cg + (size_t)(mrow + 8) * DD + ncol) =
                make_float2(c[2] + bv.x, c[3] + bv.y);
        }
    }
}

// ---------------------------------------------------------------------------
// fp16 PV GEMM: X(half) = diag(1/rowsum) * (P' @ Vb). (unchanged from R11)
// ---------------------------------------------------------------------------
__global__ void __launch_bounds__(256, 2) pv_hgemm()
{
    const int bx = blockIdx.x, by = blockIdx.y, bz = blockIdx.z;
    const int m0 = by * 128, n0 = bx * 128;

    const __half* A  = g_ph + (size_t)bz * SS * SS + (size_t)m0 * SS;
    const __half* Vp = g_v + (size_t)bz * DD + n0;
    __half* C        = g_x + (size_t)bz * DD;
    const int lda = SS, ldv = BB*DD, ldc = BB*DD;
    const int KIT = (m0 + 128) / 32;

    extern __shared__ char dsm[];
    const uint32_t dsm_u = (uint32_t)__cvta_generic_to_shared(dsm);
    __shared__ float sinv[128];

    const int tid   = threadIdx.x;
    const int warp  = tid >> 5, lane = tid & 31;
    const int group = lane >> 2, quad = lane & 3;
    const int warp_m = (warp >> 2) * 64;
    const int warp_n = (warp & 3) * 32;
    const int sel = lane >> 3, lr = lane & 7;
    const int a_row  = warp_m + (sel & 1) * 8 + lr;
    const int a_gsel = sel >> 1;
    const int a_sw   = (a_row >> 1) & 3;
    const int v_klo  = (sel & 1) * 8 + lr;
    const int v_goff = sel >> 1;

    if (tid < 128) {
        float s = 0.0f;
        const int row = m0 + tid;
        for (int jt = 0; jt <= by; jt++) {
            const float* p = g_psum + (((size_t)bz * 16 + jt) * 4) * SS + row;
            s += p[0] + p[SS] + p[2*SS] + p[3*SS];
        }
        sinv[tid] = 1.0f / s;
    }

    auto fill = [&](int s, int k0) {
        const uint32_t base = dsm_u + s * 16384;
        #pragma unroll
        for (int j = 0; j < 2; j++) {
            const int c = tid + 256 * j;
            const int row = c >> 2, g = c & 3;
            const int physA = g ^ ((row >> 1) & 3);
            cpa16(base + row * 64 + physA * 16, A + (size_t)row * lda + k0 + g * 8);
            const int krow = c >> 4, cg = c & 15;
            const int physV = cg ^ (krow & 7);
            cpa16(base + 8192 + krow * 256 + physV * 16,
                  Vp + (size_t)(k0 + krow) * ldv + cg * 8);
        }
    };

    float acc[4][4][4];
    ZERO_ACC(acc)

    auto compute = [&](int s) {
        const uint32_t aB = dsm_u + s * 16384;
        const uint32_t vB = aB + 8192;
        #pragma unroll
        for (int ks = 0; ks < 2; ks++) {
            uint32_t af[4][4];
            #pragma unroll
            for (int mi = 0; mi < 4; mi++) {
                const int row = a_row + mi * 16;
                const int phys = (ks * 2 + a_gsel) ^ a_sw;
                ldsm4(af[mi][0], af[mi][1], af[mi][2], af[mi][3],
                      aB + row * 64 + phys * 16);
            }
            uint32_t bf[4][2];
            const int krow = ks * 16 + v_klo;
            #pragma unroll
            for (int np = 0; np < 2; np++) {
                const int chunk = (warp_n >> 3) + np * 2 + v_goff;
                const int phys = chunk ^ (krow & 7);
                ldsm4t(bf[np*2][0], bf[np*2][1], bf[np*2+1][0], bf[np*2+1][1],
                       vB + krow * 256 + phys * 16);
            }
            #pragma unroll
            for (int mi = 0; mi < 4; mi++)
                #pragma unroll
                for (int ni = 0; ni < 4; ni++)
                    hmma16(acc[mi][ni], af[mi], bf[ni]);
        }
    };

    fill(0, 0);  CP_COMMIT();
    fill(1, 32); CP_COMMIT();
    for (int it = 0; it < KIT; it++) {
        cp_wait<1>();
        __syncthreads();
        compute(it % 3);
        if (it + 2 < KIT) fill((it + 2) % 3, (it + 2) * 32);
        CP_COMMIT();
    }

    #pragma unroll
    for (int mi = 0; mi < 4; mi++) {
        const int mrow = m0 + warp_m + mi * 16 + group;
        const float inv0 = sinv[mrow - m0];
        const float inv1 = sinv[mrow + 8 - m0];
        #pragma unroll
        for (int ni = 0; ni < 4; ni++) {
            const int ncol = n0 + warp_n + ni * 8 + quad * 2;
            const float* c = acc[mi][ni];
            *(__half2*)(C + (size_t)mrow * ldc + ncol) =
                __floats2half2_rn(c[0] * inv0, c[1] * inv0);
            *(__half2*)(C + (size_t)(mrow + 8) * ldc + ncol) =
                __floats2half2_rn(c[2] * inv1, c[3] * inv1);
        }
    }
}

// ---------------------------------------------------------------------------
// Fused fp32->fp16 conversion: one launch covers all 7 tensors.
// Segments: 3 inputs (16384 blocks each), 4 weights (1024 blocks each).
// Block counts are exact (no bounds guard needed).
// ---------------------------------------------------------------------------
#define NB_IN 16384
#define NB_W  1024
__global__ void __launch_bounds__(256) cvt_all_kernel(
    const float4* __restrict__ s0, const float4* __restrict__ s1, const float4* __restrict__ s2,
    const float4* __restrict__ s3, const float4* __restrict__ s4, const float4* __restrict__ s5,
    const float4* __restrict__ s6,
    __half* __restrict__ d0, __half* __restrict__ d1, __half* __restrict__ d2,
    __half* __restrict__ d3, __half* __restrict__ d4, __half* __restrict__ d5,
    __half* __restrict__ d6)
{
    int b = blockIdx.x;
    const float4* s; __half* d; int lb;
    if      (b < NB_IN)              { s = s0; d = d0; lb = b; }
    else if (b < 2*NB_IN)            { s = s1; d = d1; lb = b - NB_IN; }
    else if (b < 3*NB_IN)            { s = s2; d = d2; lb = b - 2*NB_IN; }
    else if (b < 3*NB_IN + NB_W)     { s = s3; d = d3; lb = b - 3*NB_IN; }
    else if (b < 3*NB_IN + 2*NB_W)   { s = s4; d = d4; lb = b - 3*NB_IN - NB_W; }
    else if (b < 3*NB_IN + 3*NB_W)   { s = s5; d = d5; lb = b - 3*NB_IN - 2*NB_W; }
    else                             { s = s6; d = d6; lb = b - 3*NB_IN - 3*NB_W; }

    const int i = lb * 256 + threadIdx.x;
    float4 v = s[i];
    __half2 h0 = __floats2half2_rn(v.x, v.y);
    __half2 h1 = __floats2half2_rn(v.z, v.w);
    *(uint2*)(d + (size_t)i * 4) = make_uint2(*(uint32_t*)&h0, *(uint32_t*)&h1);
}

// ---------------------------------------------------------------------------
extern "C" void kernel_launch(void* const* d_in, const int* in_sizes, int n_in,
                              void* d_out, int out_size)
{
    const float* query = (const float*)d_in[0];
    const float* key   = (const float*)d_in[1];
    const float* value = (const float*)d_in[2];
    // d_in[3] = causal mask (structure known, not read)
    const float* Wq = (const float*)d_in[4];
    const float* bq = (const float*)d_in[5];
    const float* Wk = (const float*)d_in[6];
    const float* bk = (const float*)d_in[7];
    const float* Wv = (const float*)d_in[8];
    const float* bv = (const float*)d_in[9];
    const float* Wo = (const float*)d_in[10];
    const float* bo = (const float*)d_in[11];
    float* out = (float*)d_out;

    __half *cq, *ck, *cv, *wq, *wk, *wv, *wo;
    cudaGetSymbolAddress((void**)&cq, g_cq);
    cudaGetSymbolAddress((void**)&ck, g_ck);
    cudaGetSymbolAddress((void**)&cv, g_cv);
    cudaGetSymbolAddress((void**)&wq, g_wq);
    cudaGetSymbolAddress((void**)&wk, g_wk);
    cudaGetSymbolAddress((void**)&wv, g_wv);
    cudaGetSymbolAddress((void**)&wo, g_wo);

    const int SMEM = 49152;
    cudaFuncSetAttribute(hgemm_qkv,    cudaFuncAttributeMaxDynamicSharedMemorySize, SMEM);
    cudaFuncSetAttribute(hgemm_scores, cudaFuncAttributeMaxDynamicSharedMemorySize, SMEM);
    cudaFuncSetAttribute(hgemm_oproj,  cudaFuncAttributeMaxDynamicSharedMemorySize, SMEM);
    cudaFuncSetAttribute(pv_hgemm,     cudaFuncAttributeMaxDynamicSharedMemorySize, SMEM);

    cvt_all_kernel<<<3*NB_IN + 4*NB_W, 256>>>(
        (const float4*)query, (const float4*)key, (const float4*)value,
        (const float4*)Wq, (const float4*)Wk, (const float4*)Wv, (const float4*)Wo,
        cq, ck, cv, wq, wk, wv, wo);

    hgemm_qkv<<<dim3(DD/128, SB/128, 3), 256, SMEM>>>(cq, ck, cv, bq, bk, bv);

    hgemm_scores<<<dim3(SS/128, SS/128, BB), 256, SMEM>>>();

    pv_hgemm<<<dim3(DD/128, SS/128, BB), 256, SMEM>>>();

    hgemm_oproj<<<dim3(DD/128, SB/128), 256, SMEM>>>(bo, out);
}

// round 15
// speedup vs baseline: 8.7383x; 1.0311x over previous
#include <cuda_runtime.h>
#include <cuda_fp16.h>
#include <math.h>
#include <stdint.h>

#define SS 2048
#define BB 8
#define DD 1024
#define SB (SS*BB)
#define SCALE 0.03125f  /* 1/sqrt(1024) */

static __device__ __half g_q[(size_t)SB*DD];
static __device__ __half g_k[(size_t)SB*DD];
static __device__ __half g_v[(size_t)SB*DD];
static __device__ __half g_x[(size_t)SB*DD];
static __device__ __half g_ph[(size_t)BB*SS*SS];       // half exp(scores), unnormalized
static __device__ float  g_psum[(size_t)BB*16*4*SS];   // [b][jt][wn][row] partial row sums
static __device__ __half g_cq[(size_t)SB*DD];
static __device__ __half g_ck[(size_t)SB*DD];
static __device__ __half g_cv[(size_t)SB*DD];
static __device__ __half g_wq[(size_t)DD*DD];
static __device__ __half g_wk[(size_t)DD*DD];
static __device__ __half g_wv[(size_t)DD*DD];
static __device__ __half g_wo[(size_t)DD*DD];

__device__ __forceinline__ void cpa16(uint32_t s, const void* g) {
    asm volatile("cp.async.cg.shared.global [%0], [%1], 16;" :: "r"(s), "l"(g));
}
#define CP_COMMIT() asm volatile("cp.async.commit_group;")
template<int N> __device__ __forceinline__ void cp_wait() {
    asm volatile("cp.async.wait_group %0;" :: "n"(N));
}

__device__ __forceinline__ void hmma16(float* c, const uint32_t* a, const uint32_t* b) {
    asm volatile(
        "mma.sync.aligned.m16n8k16.row.col.f32.f16.f16.f32 "
        "{%0,%1,%2,%3}, {%4,%5,%6,%7}, {%8,%9}, {%0,%1,%2,%3};"
        : "+f"(c[0]), "+f"(c[1]), "+f"(c[2]), "+f"(c[3])
        : "r"(a[0]), "r"(a[1]), "r"(a[2]), "r"(a[3]), "r"(b[0]), "r"(b[1]));
}
__device__ __forceinline__ void ldsm4(uint32_t& r0, uint32_t& r1, uint32_t& r2, uint32_t& r3, uint32_t addr) {
    asm volatile("ldmatrix.sync.aligned.m8n8.x4.shared.b16 {%0,%1,%2,%3}, [%4];"
                 : "=r"(r0), "=r"(r1), "=r"(r2), "=r"(r3) : "r"(addr));
}
__device__ __forceinline__ void ldsm4t(uint32_t& r0, uint32_t& r1, uint32_t& r2, uint32_t& r3, uint32_t addr) {
    asm volatile("ldmatrix.sync.aligned.m8n8.x4.trans.shared.b16 {%0,%1,%2,%3}, [%4];"
                 : "=r"(r0), "=r"(r1), "=r"(r2), "=r"(r3) : "r"(addr));
}

// ===========================================================================
// Shared GEMM machinery. 4-stage cp.async ring, fill issued BEFORE compute
// so prefetch distance covers ~3 compute blocks (> gmem latency).
// ===========================================================================
#define NST 4
struct GemmCtx {
    uint32_t dsm_u;
    int tid, warp, lane, group, quad;
    int warp_m, warp_n;
    int a_row, a_gsel, a_sw;
    int b_nrow, b_gsel, b_sw;
};
__device__ __forceinline__ void init_ctx(GemmCtx& g, uint32_t dsm_u) {
    g.dsm_u = dsm_u;
    g.tid = threadIdx.x;
    g.warp = g.tid >> 5; g.lane = g.tid & 31;
    g.group = g.lane >> 2; g.quad = g.lane & 3;
    g.warp_m = (g.warp >> 2) * 64;
    g.warp_n = (g.warp & 3) * 32;
    const int sel = g.lane >> 3, lr = g.lane & 7;
    g.a_row  = g.warp_m + (sel & 1) * 8 + lr;
    g.a_gsel = sel >> 1;
    g.a_sw   = (g.a_row >> 1) & 3;
    g.b_nrow = g.warp_n + (sel >> 1) * 8 + lr;
    g.b_gsel = sel & 1;
    g.b_sw   = (g.b_nrow >> 1) & 3;
}
__device__ __forceinline__ void nt_fill(const GemmCtx& g, int s, int k0,
                                        const __half* A, int lda,
                                        const __half* Bp, int ldb) {
    const uint32_t base = g.dsm_u + s * 16384;
    #pragma unroll
    for (int j = 0; j < 2; j++) {
        const int c = g.tid + 256 * j;
        const int row = c >> 2, gg = c & 3;
        const int phys = gg ^ ((row >> 1) & 3);
        cpa16(base + row * 64 + phys * 16,        A  + (size_t)row * lda + k0 + gg * 8);
        cpa16(base + 8192 + row * 64 + phys * 16, Bp + (size_t)row * ldb + k0 + gg * 8);
    }
}
__device__ __forceinline__ void nt_compute(const GemmCtx& g, int s, float acc[4][4][4]) {
    const uint32_t aB = g.dsm_u + s * 16384;
    const uint32_t bB = aB + 8192;
    #pragma unroll
    for (int ks = 0; ks < 2; ks++) {
        uint32_t af[4][4];
        #pragma unroll
        for (int mi = 0; mi < 4; mi++) {
            const int row = g.a_row + mi * 16;
            const int phys = (ks * 2 + g.a_gsel) ^ g.a_sw;
            ldsm4(af[mi][0], af[mi][1], af[mi][2], af[mi][3],
                  aB + row * 64 + phys * 16);
        }
        uint32_t bf[4][2];
        #pragma unroll
        for (int np = 0; np < 2; np++) {
            const int nr = g.b_nrow + np * 16;
            const int phys = (ks * 2 + g.b_gsel) ^ g.b_sw;
            ldsm4(bf[np*2][0], bf[np*2][1], bf[np*2+1][0], bf[np*2+1][1],
                  bB + nr * 64 + phys * 16);
        }
        #pragma unroll
        for (int mi = 0; mi < 4; mi++)
            #pragma unroll
            for (int ni = 0; ni < 4; ni++)
                hmma16(acc[mi][ni], af[mi], bf[ni]);
    }
}
#define ZERO_ACC(acc) \
    _Pragma("unroll") for (int mi = 0; mi < 4; mi++) \
        _Pragma("unroll") for (int ni = 0; ni < 4; ni++) \
            _Pragma("unroll") for (int r = 0; r < 4; r++) acc[mi][ni][r] = 0.0f;

// Pipelined mainloop macro: prologue fills stages 0..2, then per iteration:
// wait(stage it ready) -> barrier -> fill(it+3) -> compute(it).
#define NT_MAINLOOP(g, acc, KIT, A, lda, Bp, ldb)                           \
    nt_fill(g, 0, 0,  A, lda, Bp, ldb); CP_COMMIT();                        \
    nt_fill(g, 1, 32, A, lda, Bp, ldb); CP_COMMIT();                        \
    nt_fill(g, 2, 64, A, lda, Bp, ldb); CP_COMMIT();                        \
    for (int it = 0; it < KIT; it++) {                                      \
        cp_wait<2>();                                                       \
        __syncthreads();                                                    \
        if (it + 3 < KIT)                                                   \
            nt_fill(g, (it + 3) % NST, (it + 3) * 32, A, lda, Bp, ldb);     \
        CP_COMMIT();                                                        \
        nt_compute(g, it % NST, acc);                                       \
    }

// ---------------------------------------------------------------------------
// Batched QKV projection: z selects (input, weight, bias, output).
// ---------------------------------------------------------------------------
__global__ void __launch_bounds__(256, 2) hgemm_qkv(
    const __half* __restrict__ A0, const __half* __restrict__ A1, const __half* __restrict__ A2,
    const float* __restrict__ b0, const float* __restrict__ b1, const float* __restrict__ b2)
{
    const int bx = blockIdx.x, by = blockIdx.y, bz = blockIdx.z;
    const int m0 = by * 128, n0 = bx * 128;

    const __half* Ag = (bz == 0) ? A0 : (bz == 1) ? A1 : A2;
    const __half* Wg = (bz == 0) ? g_wq : (bz == 1) ? g_wk : g_wv;
    const float*  bias = (bz == 0) ? b0 : (bz == 1) ? b1 : b2;
    __half* Cg = (bz == 0) ? g_q : (bz == 1) ? g_k : g_v;

    const __half* A  = Ag + (size_t)m0 * DD;
    const __half* Bp = Wg + (size_t)n0 * DD;
    const int KIT = DD / 32;

    extern __shared__ char dsm[];
    GemmCtx g; init_ctx(g, (uint32_t)__cvta_generic_to_shared(dsm));

    float acc[4][4][4];
    ZERO_ACC(acc)

    NT_MAINLOOP(g, acc, KIT, A, DD, Bp, DD)

    #pragma unroll
    for (int mi = 0; mi < 4; mi++) {
        const int mrow = m0 + g.warp_m + mi * 16 + g.group;
        #pragma unroll
        for (int ni = 0; ni < 4; ni++) {
            const int ncol = n0 + g.warp_n + ni * 8 + g.quad * 2;
            const float* c = acc[mi][ni];
            float2 bv = *(const float2*)(bias + ncol);
            *(__half2*)(Cg + (size_t)mrow * DD + ncol) =
                __floats2half2_rn(c[0] + bv.x, c[1] + bv.y);
            *(__half2*)(Cg + (size_t)(mrow + 8) * DD + ncol) =
                __floats2half2_rn(c[2] + bv.x, c[3] + bv.y);
        }
    }
}

// ---------------------------------------------------------------------------
// Scores: g_ph(half) = exp(SCALE * Qb@Kb^T) masked causal, psum partials.
// ---------------------------------------------------------------------------
__global__ void __launch_bounds__(256, 2) hgemm_scores()
{
    const int bx = blockIdx.x, by = blockIdx.y, bz = blockIdx.z;
    if (bx > by) return;
    const int m0 = by * 128, n0 = bx * 128;

    const __half* A  = g_q + (size_t)bz * DD + (size_t)m0 * (BB*DD);
    const __half* Bp = g_k + (size_t)bz * DD + (size_t)n0 * (BB*DD);
    const int KIT = DD / 32;

    extern __shared__ char dsm[];
    GemmCtx g; init_ctx(g, (uint32_t)__cvta_generic_to_shared(dsm));

    float acc[4][4][4];
    ZERO_ACC(acc)

    NT_MAINLOOP(g, acc, KIT, A, BB*DD, Bp, BB*DD)

    __half* C = g_ph + (size_t)bz * SS * SS;
    float* psum = g_psum + (((size_t)bz * 16 + bx) * 4 + (g.warp & 3)) * SS;
    #pragma unroll
    for (int mi = 0; mi < 4; mi++) {
        const int r0 = m0 + g.warp_m + mi * 16 + g.group;
        const int r1 = r0 + 8;
        float s0 = 0.0f, s1 = 0.0f;
        #pragma unroll
        for (int ni = 0; ni < 4; ni++) {
            const int ncol = n0 + g.warp_n + ni * 8 + g.quad * 2;
            const float* c = acc[mi][ni];
            float p0 = (ncol     <= r0) ? expf(c[0] * SCALE) : 0.0f;
            float p1 = (ncol + 1 <= r0) ? expf(c[1] * SCALE) : 0.0f;
            float p2 = (ncol     <= r1) ? expf(c[2] * SCALE) : 0.0f;
            float p3 = (ncol + 1 <= r1) ? expf(c[3] * SCALE) : 0.0f;
            s0 += p0 + p1;
            s1 += p2 + p3;
            *(__half2*)(C + (size_t)r0 * SS + ncol) = __floats2half2_rn(p0, p1);
            *(__half2*)(C + (size_t)r1 * SS + ncol) = __floats2half2_rn(p2, p3);
        }
        s0 += __shfl_xor_sync(0xffffffffu, s0, 1);
        s0 += __shfl_xor_sync(0xffffffffu, s0, 2);
        s1 += __shfl_xor_sync(0xffffffffu, s1, 1);
        s1 += __shfl_xor_sync(0xffffffffu, s1, 2);
        if (g.quad == 0) { psum[r0] = s0; psum[r1] = s1; }
    }
}

// ---------------------------------------------------------------------------
// Output projection: C(fp32) = A @ W^T + bias -> d_out
// ---------------------------------------------------------------------------
__global__ void __launch_bounds__(256, 2) hgemm_oproj(
    const float* __restrict__ bias, float* __restrict__ Cg)
{
    const int bx = blockIdx.x, by = blockIdx.y;
    const int m0 = by * 128, n0 = bx * 128;

    const __half* A  = g_x + (size_t)m0 * DD;
    const __half* Bp = g_wo + (size_t)n0 * DD;
    const int KIT = DD / 32;

    extern __shared__ char dsm[];
    GemmCtx g; init_ctx(g, (uint32_t)__cvta_generic_to_shared(dsm));

    float acc[4][4][4];
    ZERO_ACC(acc)

    NT_MAINLOOP(g, acc, KIT, A, DD, Bp, DD)

    #pragma unroll
    for (int mi = 0; mi < 4; mi++) {
        const int mrow = m0 + g.warp_m + mi * 16 + g.group;
        #pragma unroll
        for (int ni = 0; ni < 4; ni++) {
            const int ncol = n0 + g.warp_n + ni * 8 + g.quad * 2;
            const float* c = acc[mi][ni];
            float2 bv = *(const float2*)(bias + ncol);
            *(float2*)(Cg + (size_t)mrow * DD + ncol) =
                make_float2(c[0] + bv.x, c[1] + bv.y);
            *(float2*)(Cg + (size_t)(mrow + 8) * DD + ncol) =
                make_float2(c[2] + bv.x, c[3] + bv.y);
        }
    }
}

// ---------------------------------------------------------------------------
// fp16 PV GEMM: X(half) = diag(1/rowsum) * (P' @ Vb). 4-stage, fill-early.
// ---------------------------------------------------------------------------
__global__ void __launch_bounds__(256, 2) pv_hgemm()
{
    const int bx = blockIdx.x, by = blockIdx.y, bz = blockIdx.z;
    const int m0 = by * 128, n0 = bx * 128;

    const __half* A  = g_ph + (size_t)bz * SS * SS + (size_t)m0 * SS;
    const __half* Vp = g_v + (size_t)bz * DD + n0;
    __half* C        = g_x + (size_t)bz * DD;
    const int lda = SS, ldv = BB*DD, ldc = BB*DD;
    const int KIT = (m0 + 128) / 32;

    extern __shared__ char dsm[];
    const uint32_t dsm_u = (uint32_t)__cvta_generic_to_shared(dsm);
    __shared__ float sinv[128];

    const int tid   = threadIdx.x;
    const int warp  = tid >> 5, lane = tid & 31;
    const int group = lane >> 2, quad = lane & 3;
    const int warp_m = (warp >> 2) * 64;
    const int warp_n = (warp & 3) * 32;
    const int sel = lane >> 3, lr = lane & 7;
    const int a_row  = warp_m + (sel & 1) * 8 + lr;
    const int a_gsel = sel >> 1;
    const int a_sw   = (a_row >> 1) & 3;
    const int v_klo  = (sel & 1) * 8 + lr;
    const int v_goff = sel >> 1;

    if (tid < 128) {
        float s = 0.0f;
        const int row = m0 + tid;
        for (int jt = 0; jt <= by; jt++) {
            const float* p = g_psum + (((size_t)bz * 16 + jt) * 4) * SS + row;
            s += p[0] + p[SS] + p[2*SS] + p[3*SS];
        }
        sinv[tid] = 1.0f / s;
    }

    auto fill = [&](int s, int k0) {
        const uint32_t base = dsm_u + s * 16384;
        #pragma unroll
        for (int j = 0; j < 2; j++) {
            const int c = tid + 256 * j;
            const int row = c >> 2, g = c & 3;
            const int physA = g ^ ((row >> 1) & 3);
            cpa16(base + row * 64 + physA * 16, A + (size_t)row * lda + k0 + g * 8);
            const int krow = c >> 4, cg = c & 15;
            const int physV = cg ^ (krow & 7);
            cpa16(base + 8192 + krow * 256 + physV * 16,
                  Vp + (size_t)(k0 + krow) * ldv + cg * 8);
        }
    };

    float acc[4][4][4];
    ZERO_ACC(acc)

    auto compute = [&](int s) {
        const uint32_t aB = dsm_u + s * 16384;
        const uint32_t vB = aB + 8192;
        #pragma unroll
        for (int ks = 0; ks < 2; ks++) {
            uint32_t af[4][4];
            #pragma unroll
            for (int mi = 0; mi < 4; mi++) {
                const int row = a_row + mi * 16;
                const int phys = (ks * 2 + a_gsel) ^ a_sw;
                ldsm4(af[mi][0], af[mi][1], af[mi][2], af[mi][3],
                      aB + row * 64 + phys * 16);
            }
            uint32_t bf[4][2];
            const int krow = ks * 16 + v_klo;
            #pragma unroll
            for (int np = 0; np < 2; np++) {
                const int chunk = (warp_n >> 3) + np * 2 + v_goff;
                const int phys = chunk ^ (krow & 7);
                ldsm4t(bf[np*2][0], bf[np*2][1], bf[np*2+1][0], bf[np*2+1][1],
                       vB + krow * 256 + phys * 16);
            }
            #pragma unroll
            for (int mi = 0; mi < 4; mi++)
                #pragma unroll
                for (int ni = 0; ni < 4; ni++)
                    hmma16(acc[mi][ni], af[mi], bf[ni]);
        }
    };

    fill(0, 0);  CP_COMMIT();
    fill(1, 32); CP_COMMIT();
    fill(2, 64); CP_COMMIT();
    for (int it = 0; it < KIT; it++) {
        cp_wait<2>();
        __syncthreads();
        if (it + 3 < KIT) fill((it + 3) % NST, (it + 3) * 32);
        CP_COMMIT();
        compute(it % NST);
    }

    #pragma unroll
    for (int mi = 0; mi < 4; mi++) {
        const int mrow = m0 + warp_m + mi * 16 + group;
        const float inv0 = sinv[mrow - m0];
        const float inv1 = sinv[mrow + 8 - m0];
        #pragma unroll
        for (int ni = 0; ni < 4; ni++) {
            const int ncol = n0 + warp_n + ni * 8 + quad * 2;
            const float* c = acc[mi][ni];
            *(__half2*)(C + (size_t)mrow * ldc + ncol) =
                __floats2half2_rn(c[0] * inv0, c[1] * inv0);
            *(__half2*)(C + (size_t)(mrow + 8) * ldc + ncol) =
                __floats2half2_rn(c[2] * inv1, c[3] * inv1);
        }
    }
}

// ---------------------------------------------------------------------------
// Fused fp32->fp16 conversion: one launch covers all 7 tensors.
// ---------------------------------------------------------------------------
#define NB_IN 16384
#define NB_W  1024
__global__ void __launch_bounds__(256) cvt_all_kernel(
    const float4* __restrict__ s0, const float4* __restrict__ s1, const float4* __restrict__ s2,
    const float4* __restrict__ s3, const float4* __restrict__ s4, const float4* __restrict__ s5,
    const float4* __restrict__ s6,
    __half* __restrict__ d0, __half* __restrict__ d1, __half* __restrict__ d2,
    __half* __restrict__ d3, __half* __restrict__ d4, __half* __restrict__ d5,
    __half* __restrict__ d6)
{
    int b = blockIdx.x;
    const float4* s; __half* d; int lb;
    if      (b < NB_IN)              { s = s0; d = d0; lb = b; }
    else if (b < 2*NB_IN)            { s = s1; d = d1; lb = b - NB_IN; }
    else if (b < 3*NB_IN)            { s = s2; d = d2; lb = b - 2*NB_IN; }
    else if (b < 3*NB_IN + NB_W)     { s = s3; d = d3; lb = b - 3*NB_IN; }
    else if (b < 3*NB_IN + 2*NB_W)   { s = s4; d = d4; lb = b - 3*NB_IN - NB_W; }
    else if (b < 3*NB_IN + 3*NB_W)   { s = s5; d = d5; lb = b - 3*NB_IN - 2*NB_W; }
    else                             { s = s6; d = d6; lb = b - 3*NB_IN - 3*NB_W; }

    const int i = lb * 256 + threadIdx.x;
    float4 v = s[i];
    __half2 h0 = __floats2half2_rn(v.x, v.y);
    __half2 h1 = __floats2half2_rn(v.z, v.w);
    *(uint2*)(d + (size_t)i * 4) = make_uint2(*(uint32_t*)&h0, *(uint32_t*)&h1);
}

// ---------------------------------------------------------------------------
extern "C" void kernel_launch(void* const* d_in, const int* in_sizes, int n_in,
                              void* d_out, int out_size)
{
    const float* query = (const float*)d_in[0];
    const float* key   = (const float*)d_in[1];
    const float* value = (const float*)d_in[2];
    // d_in[3] = causal mask (structure known, not read)
    const float* Wq = (const float*)d_in[4];
    const float* bq = (const float*)d_in[5];
    const float* Wk = (const float*)d_in[6];
    const float* bk = (const float*)d_in[7];
    const float* Wv = (const float*)d_in[8];
    const float* bv = (const float*)d_in[9];
    const float* Wo = (const float*)d_in[10];
    const float* bo = (const float*)d_in[11];
    float* out = (float*)d_out;

    __half *cq, *ck, *cv, *wq, *wk, *wv, *wo;
    cudaGetSymbolAddress((void**)&cq, g_cq);
    cudaGetSymbolAddress((void**)&ck, g_ck);
    cudaGetSymbolAddress((void**)&cv, g_cv);
    cudaGetSymbolAddress((void**)&wq, g_wq);
    cudaGetSymbolAddress((void**)&wk, g_wk);
    cudaGetSymbolAddress((void**)&wv, g_wv);
    cudaGetSymbolAddress((void**)&wo, g_wo);

    const int SMEM = NST * 16384;   // 65536
    cudaFuncSetAttribute(hgemm_qkv,    cudaFuncAttributeMaxDynamicSharedMemorySize, SMEM);
    cudaFuncSetAttribute(hgemm_scores, cudaFuncAttributeMaxDynamicSharedMemorySize, SMEM);
    cudaFuncSetAttribute(hgemm_oproj,  cudaFuncAttributeMaxDynamicSharedMemorySize, SMEM);
    cudaFuncSetAttribute(pv_hgemm,     cudaFuncAttributeMaxDynamicSharedMemorySize, SMEM);

    cvt_all_kernel<<<3*NB_IN + 4*NB_W, 256>>>(
        (const float4*)query, (const float4*)key, (const float4*)value,
        (const float4*)Wq, (const float4*)Wk, (const float4*)Wv, (const float4*)Wo,
        cq, ck, cv, wq, wk, wv, wo);

    hgemm_qkv<<<dim3(DD/128, SB/128, 3), 256, SMEM>>>(cq, ck, cv, bq, bk, bv);

    hgemm_scores<<<dim3(SS/128, SS/128, BB), 256, SMEM>>>();

    pv_hgemm<<<dim3(DD/128, SS/128, BB), 256, SMEM>>>();

    hgemm_oproj<<<dim3(DD/128, SB/128), 256, SMEM>>>(bo, out);
}